// round 1
// baseline (speedup 1.0000x reference)
#include <cuda_runtime.h>
#include <math.h>

#define NB   8
#define LDQ  2048
#define LMEM 512
#define DIN  1024
#define HID  1024

// Scratch (allocation-free rule -> __device__ globals)
__device__ float g_input_dot[(size_t)NB * LDQ * HID];    // 64 MB
__device__ float g_memory_dot[(size_t)NB * LMEM * HID];  // 16 MB
__device__ float g_att[(size_t)NB * LDQ * LMEM];         // 32 MB
__device__ float g_out_one[(size_t)NB * LDQ * DIN];      // 64 MB

enum { ACT_NONE = 0, ACT_RELU = 1, ACT_GATE = 2 };

// Classic 128x128x8 register-blocked SGEMM. 256 threads, 8x8 per thread.
// TRANSB: B is [N,K] row-major (NT gemm). Dual-A: for k >= Ksplit read A2
// (used to fuse the concat([x, out_one]) @ W2 GEMM). All dims are multiples
// of tile sizes for this problem, so no bounds checks.
template <bool TRANSB, int ACT>
__global__ void __launch_bounds__(256)
sgemm_k(const float* __restrict__ A1, const float* __restrict__ A2,
        const float* __restrict__ B, const float* __restrict__ bias,
        float* __restrict__ C,
        int N, int K, int Ksplit, int lda, int ldb,
        long long sA, long long sB, long long sC, float scale)
{
    const int BM = 128, BN = 128, BK = 8;
    __shared__ float As[BK][BM];
    __shared__ float Bs[BK][BN];

    const int z = blockIdx.z;
    A1 += (size_t)z * sA;
    A2 += (size_t)z * sA;
    B  += (size_t)z * sB;
    C  += (size_t)z * sC;

    const int t  = threadIdx.x;
    const int m0 = blockIdx.y * BM;
    const int n0 = blockIdx.x * BN;

    // A tile loader: thread -> (row, 4 contiguous k)
    const int a_m = t >> 1;
    const int a_k = (t & 1) * 4;
    // B tile loader (NN): thread -> (k row, 4 contiguous n)
    const int b_k = t >> 5;
    const int b_n = (t & 31) * 4;
    // B tile loader (NT): thread -> (n row, 4 contiguous k)
    const int bt_n = t >> 1;
    const int bt_k = (t & 1) * 4;

    const int tx = t & 15;
    const int ty = t >> 4;

    float acc[8][8];
#pragma unroll
    for (int i = 0; i < 8; i++)
#pragma unroll
        for (int j = 0; j < 8; j++) acc[i][j] = 0.0f;

    for (int k0 = 0; k0 < K; k0 += BK) {
        // ---- load A tile (dual-source for fused concat GEMM) ----
        const float* Ap = (k0 < Ksplit) ? A1 : A2;
        const int ka = (k0 < Ksplit) ? k0 : (k0 - Ksplit);
        float4 av = *(const float4*)&Ap[(size_t)(m0 + a_m) * lda + ka + a_k];
        As[a_k + 0][a_m] = av.x;
        As[a_k + 1][a_m] = av.y;
        As[a_k + 2][a_m] = av.z;
        As[a_k + 3][a_m] = av.w;

        // ---- load B tile ----
        if (!TRANSB) {
            float4 bv = *(const float4*)&B[(size_t)(k0 + b_k) * ldb + n0 + b_n];
            *(float4*)&Bs[b_k][b_n] = bv;
        } else {
            float4 bv = *(const float4*)&B[(size_t)(n0 + bt_n) * ldb + k0 + bt_k];
            Bs[bt_k + 0][bt_n] = bv.x;
            Bs[bt_k + 1][bt_n] = bv.y;
            Bs[bt_k + 2][bt_n] = bv.z;
            Bs[bt_k + 3][bt_n] = bv.w;
        }
        __syncthreads();

#pragma unroll
        for (int kk = 0; kk < BK; kk++) {
            float4 a0 = *(const float4*)&As[kk][ty * 8];
            float4 a1 = *(const float4*)&As[kk][ty * 8 + 4];
            float4 b0 = *(const float4*)&Bs[kk][tx * 8];
            float4 b1 = *(const float4*)&Bs[kk][tx * 8 + 4];
            float ar[8] = {a0.x, a0.y, a0.z, a0.w, a1.x, a1.y, a1.z, a1.w};
            float br[8] = {b0.x, b0.y, b0.z, b0.w, b1.x, b1.y, b1.z, b1.w};
#pragma unroll
            for (int i = 0; i < 8; i++)
#pragma unroll
                for (int j = 0; j < 8; j++)
                    acc[i][j] = fmaf(ar[i], br[j], acc[i][j]);
        }
        __syncthreads();
    }

    // ---- epilogue ----
#pragma unroll
    for (int i = 0; i < 8; i++) {
        const int m = m0 + ty * 8 + i;
#pragma unroll
        for (int j = 0; j < 8; j++) {
            const int n = n0 + tx * 8 + j;
            float v = acc[i][j] * scale;
            if (bias) v += bias[n];
            if (ACT == ACT_RELU) v = fmaxf(v, 0.0f);
            if (ACT == ACT_GATE) {
                float s = 1.0f / (1.0f + expf(-v));
                v = s * tanhf(v);
            }
            C[(size_t)m * N + n] = v;
        }
    }
}

// Masked softmax over last dim (512). One block (256 threads) per row.
__global__ void softmax_k(float* __restrict__ att, const float* __restrict__ mask)
{
    const int row = blockIdx.x;
    const int b = row / LDQ;
    float* p = att + (size_t)row * LMEM;
    const float* mk = mask + (size_t)b * LMEM;
    const int t = threadIdx.x;

    float v0 = p[t] - 1e30f * (1.0f - mk[t]);
    float v1 = p[t + 256] - 1e30f * (1.0f - mk[t + 256]);

    __shared__ float red[256];
    red[t] = fmaxf(v0, v1);
    __syncthreads();
#pragma unroll
    for (int s = 128; s > 0; s >>= 1) {
        if (t < s) red[t] = fmaxf(red[t], red[t + s]);
        __syncthreads();
    }
    const float rm = red[0];
    __syncthreads();

    const float e0 = __expf(v0 - rm);
    const float e1 = __expf(v1 - rm);
    red[t] = e0 + e1;
    __syncthreads();
#pragma unroll
    for (int s = 128; s > 0; s >>= 1) {
        if (t < s) red[t] += red[t + s];
        __syncthreads();
    }
    const float inv = 1.0f / red[0];
    p[t] = e0 * inv;
    p[t + 256] = e1 * inv;
}

__global__ void copy_k(const float4* __restrict__ src, float4* __restrict__ dst, int n4)
{
    int i = blockIdx.x * blockDim.x + threadIdx.x;
    if (i < n4) dst[i] = src[i];
}

extern "C" void kernel_launch(void* const* d_in, const int* in_sizes, int n_in,
                              void* d_out, int out_size)
{
    const float* x    = (const float*)d_in[0];
    const float* mem  = (const float*)d_in[1];
    const float* mask = (const float*)d_in[2];
    const float* W1   = (const float*)d_in[3];
    const float* b1   = (const float*)d_in[4];
    const float* Wm   = (const float*)d_in[5];
    const float* bm   = (const float*)d_in[6];
    const float* W2   = (const float*)d_in[7];
    const float* b2   = (const float*)d_in[8];
    float* out = (float*)d_out;

    float *p_id, *p_md, *p_att, *p_oo;
    cudaGetSymbolAddress((void**)&p_id,  g_input_dot);
    cudaGetSymbolAddress((void**)&p_md,  g_memory_dot);
    cudaGetSymbolAddress((void**)&p_att, g_att);
    cudaGetSymbolAddress((void**)&p_oo,  g_out_one);

    dim3 blk(256);

    // 1) input_dot = relu(x @ W1 + b1)   [16384,1024]
    sgemm_k<false, ACT_RELU><<<dim3(HID / 128, (NB * LDQ) / 128, 1), blk>>>(
        x, x, W1, b1, p_id, HID, DIN, DIN, DIN, HID, 0, 0, 0, 1.0f);

    // 2) memory_dot = relu(mem @ Wm + bm)  [4096,1024]
    sgemm_k<false, ACT_RELU><<<dim3(HID / 128, (NB * LMEM) / 128, 1), blk>>>(
        mem, mem, Wm, bm, p_md, HID, DIN, DIN, DIN, HID, 0, 0, 0, 1.0f);

    // 3) att = input_dot @ memory_dot^T / 32   batched [8][2048,512]
    sgemm_k<true, ACT_NONE><<<dim3(LMEM / 128, LDQ / 128, NB), blk>>>(
        p_id, p_id, p_md, nullptr, p_att, LMEM, HID, HID, HID, HID,
        (long long)LDQ * HID, (long long)LMEM * HID, (long long)LDQ * LMEM,
        1.0f / 32.0f);

    // 4) masked softmax over memory axis
    softmax_k<<<NB * LDQ, 256>>>(p_att, mask);

    // 5) out_one = att @ mem   batched [8][2048,1024], K=512
    sgemm_k<false, ACT_NONE><<<dim3(DIN / 128, LDQ / 128, NB), blk>>>(
        p_att, p_att, mem, nullptr, p_oo, DIN, LMEM, LMEM, LMEM, DIN,
        (long long)LDQ * LMEM, (long long)LMEM * DIN, (long long)LDQ * DIN,
        1.0f);

    // 6) out = gate(x @ W2[:1024] + out_one @ W2[1024:] + b2)  [16384,1024]
    sgemm_k<false, ACT_GATE><<<dim3(HID / 128, (NB * LDQ) / 128, 1), blk>>>(
        x, p_oo, W2, b2, out, HID, 2 * DIN, DIN, DIN, HID, 0, 0, 0, 1.0f);

    // 7) second tuple element: mem passthrough
    const int n4 = (NB * LMEM * DIN) / 4;
    copy_k<<<(n4 + 255) / 256, 256>>>((const float4*)mem,
                                      (float4*)(out + (size_t)NB * LDQ * HID), n4);
}

// round 5
// speedup vs baseline: 3.0593x; 3.0593x over previous
#include <cuda_runtime.h>
#include <cstdint>
#include <math.h>

#define NB   8
#define LDQ  2048
#define LMEM 512
#define DIN  1024
#define HID  1024

// ---------------- scratch (__device__ globals; no allocations allowed) ----
__device__ float g_input_dot[(size_t)NB * LDQ * HID];    // 64 MB
__device__ float g_memory_dot[(size_t)NB * LMEM * HID];  // 16 MB
__device__ float g_att[(size_t)NB * LDQ * LMEM];         // 32 MB
__device__ float g_out_one[(size_t)NB * LDQ * DIN];      // 64 MB
__device__ float g_w1t[(size_t)DIN * HID];               // 4 MB
__device__ float g_wmt[(size_t)DIN * HID];               // 4 MB
__device__ float g_w2t[(size_t)2 * DIN * HID];           // 8 MB (W2^T: [1024, 2048])
__device__ float g_memt[(size_t)NB * DIN * LMEM];        // 16 MB (mem^T per batch)
__device__ float g_xr[(size_t)NB * LDQ * DIN];           // 64 MB (x, tf32-rounded)
__device__ float g_memr[(size_t)NB * LMEM * DIN];        // 16 MB (mem, tf32-rounded)

enum { ACT_NONE = 0, ACT_RELU = 1, ACT_GATE = 2 };

// ---------------- helpers --------------------------------------------------
__device__ __forceinline__ uint32_t smem_u32(const void* p) {
    uint32_t a;
    asm("{ .reg .u64 t; cvta.to.shared.u64 t, %1; cvt.u32.u64 %0, t; }" : "=r"(a) : "l"(p));
    return a;
}
__device__ __forceinline__ float f2tf(float f) {   // round-to-nearest tf32, as fp32
    uint32_t u;
    asm("cvt.rna.tf32.f32 %0, %1;" : "=r"(u) : "f"(f));
    return __uint_as_float(u);
}

#define CP16(dst, src) \
    asm volatile("cp.async.cg.shared.global [%0], [%1], 16;" :: "r"(dst), "l"(src))
#define CP_COMMIT() asm volatile("cp.async.commit_group;")
#define CP_WAIT1()  asm volatile("cp.async.wait_group 1;")

__device__ __forceinline__ void mma_tf32(float* d, const uint32_t* a, const uint32_t* b) {
    asm volatile(
        "mma.sync.aligned.m16n8k8.row.col.f32.tf32.tf32.f32 "
        "{%0,%1,%2,%3}, {%4,%5,%6,%7}, {%8,%9}, {%0,%1,%2,%3};"
        : "+f"(d[0]), "+f"(d[1]), "+f"(d[2]), "+f"(d[3])
        : "r"(a[0]), "r"(a[1]), "r"(a[2]), "r"(a[3]), "r"(b[0]), "r"(b[1]));
}

// ---------------- tf32 mma.sync NT GEMM: C[M,N] = A[M,K] * B[N,K]^T -------
// BM=128, BN=256, BK=16. 256 threads, 8 warps (2x4), warp tile 64x64.
// 3-stage cp.async pipeline. Smem rows padded to 20 floats (conflict-free).
static constexpr int ASZ = 128 * 20;          // floats per A stage
static constexpr int BSZ = 256 * 20;          // floats per B stage
static constexpr int STAGES = 3;
static constexpr int GEMM_SMEM = (ASZ + BSZ) * STAGES * 4;   // 92160 B

// NOTE: separate K indices: ka for the (possibly switched) A source,
// kb = global k0 for B. (Round-3 bug: shared index corrupted the DUALA GEMM.)
__device__ __forceinline__ void load_tile(
    uint32_t sb, int s, const float* __restrict__ Ap, const float* __restrict__ Bp,
    int m0, int n0, int ka, int kb, int lda, int ldb, int t)
{
    const uint32_t as = sb + s * (ASZ * 4);
    const uint32_t bs = sb + STAGES * (ASZ * 4) + s * (BSZ * 4);
    const int r  = t >> 2;
    const int c4 = (t & 3) * 4;
    const float* ag = &Ap[(size_t)(m0 + r) * lda + ka + c4];
    CP16(as + (r * 20 + c4) * 4, ag);
    CP16(as + ((r + 64) * 20 + c4) * 4, ag + (size_t)64 * lda);
    const float* bg = &Bp[(size_t)(n0 + r) * ldb + kb + c4];
#pragma unroll
    for (int q = 0; q < 4; q++)
        CP16(bs + ((r + q * 64) * 20 + c4) * 4, bg + (size_t)(q * 64) * ldb);
    CP_COMMIT();
}

template <int ACT, bool DUALA, bool ROUND>
__global__ void __launch_bounds__(256, 1)
mma_gemm(const float* __restrict__ A1, const float* __restrict__ A2,
         const float* __restrict__ B, const float* __restrict__ bias,
         float* __restrict__ C,
         int K, int Ksplit, int lda, int ldb, int ldc,
         long long sA, long long sB, long long sC, float scale)
{
    extern __shared__ float sm[];
    const uint32_t sb = smem_u32(sm);

    const int t    = threadIdx.x;
    const int wid  = t >> 5;
    const int lane = t & 31;
    const int gid  = lane >> 2;      // 0..7
    const int tig  = lane & 3;       // 0..3
    const int z = blockIdx.z;
    A1 += (size_t)z * sA;
    A2 += (size_t)z * sA;
    B  += (size_t)z * sB;
    C  += (size_t)z * sC;
    const int m0 = blockIdx.y * 128;
    const int n0 = blockIdx.x * 256;

    const int NI = K >> 4;

    // prologue: prefetch 2 stages
#pragma unroll
    for (int s = 0; s < 2; s++) {
        const int k0 = s * 16;
        const float* Ap = A1;
        int ka = k0;
        if (DUALA && k0 >= Ksplit) { Ap = A2; ka = k0 - Ksplit; }
        load_tile(sb, s, Ap, B, m0, n0, ka, k0, lda, ldb, t);
    }

    float acc[4][8][4];
#pragma unroll
    for (int i = 0; i < 4; i++)
#pragma unroll
        for (int j = 0; j < 8; j++)
#pragma unroll
            for (int q = 0; q < 4; q++) acc[i][j][q] = 0.0f;

    const int mb = (wid >> 2) * 64;   // warp row offset in tile
    const int nb = (wid & 3) * 64;    // warp col offset in tile

    for (int i = 0; i < NI; i++) {
        CP_WAIT1();
        __syncthreads();

        const int s = i % STAGES;
        const uint32_t* As_ = (const uint32_t*)(sm + s * ASZ);
        const uint32_t* Bs_ = (const uint32_t*)(sm + STAGES * ASZ + s * BSZ);

#pragma unroll
        for (int ks = 0; ks < 2; ks++) {
            const int kc = ks * 8 + tig;
            uint32_t af[4][4];
#pragma unroll
            for (int mi = 0; mi < 4; mi++) {
                const int r = mb + mi * 16 + gid;
                af[mi][0] = As_[r * 20 + kc];
                af[mi][1] = As_[(r + 8) * 20 + kc];
                af[mi][2] = As_[r * 20 + kc + 4];
                af[mi][3] = As_[(r + 8) * 20 + kc + 4];
            }
            uint32_t bf[8][2];
#pragma unroll
            for (int nj = 0; nj < 8; nj++) {
                const int n = nb + nj * 8 + gid;
                bf[nj][0] = Bs_[n * 20 + kc];
                bf[nj][1] = Bs_[n * 20 + kc + 4];
            }
#pragma unroll
            for (int mi = 0; mi < 4; mi++)
#pragma unroll
                for (int nj = 0; nj < 8; nj++)
                    mma_tf32(acc[mi][nj], af[mi], bf[nj]);
        }
        __syncthreads();

        const int nx = i + 2;
        if (nx < NI) {
            const int k0 = nx * 16;
            const float* Ap = A1;
            int ka = k0;
            if (DUALA && k0 >= Ksplit) { Ap = A2; ka = k0 - Ksplit; }
            load_tile(sb, nx % STAGES, Ap, B, m0, n0, ka, k0, lda, ldb, t);
        } else {
            CP_COMMIT();
        }
    }

    // ---- epilogue ----
#pragma unroll
    for (int mi = 0; mi < 4; mi++) {
        const int r0 = m0 + mb + mi * 16 + gid;
#pragma unroll
        for (int nj = 0; nj < 8; nj++) {
            const int c0 = n0 + nb + nj * 8 + tig * 2;
            float v[4];
#pragma unroll
            for (int q = 0; q < 4; q++) v[q] = acc[mi][nj][q] * scale;
            if (ACT != ACT_NONE) {
                const float bb0 = __ldg(&bias[c0]);
                const float bb1 = __ldg(&bias[c0 + 1]);
                v[0] += bb0; v[1] += bb1; v[2] += bb0; v[3] += bb1;
            }
#pragma unroll
            for (int q = 0; q < 4; q++) {
                if (ACT == ACT_RELU) v[q] = fmaxf(v[q], 0.0f);
                if (ACT == ACT_GATE) {
                    const float sg = 1.0f / (1.0f + expf(-v[q]));
                    v[q] = sg * tanhf(v[q]);
                }
                if (ROUND) v[q] = f2tf(v[q]);   // next consumer is a tf32 mma
            }
            *(float2*)&C[(size_t)r0 * ldc + c0]       = make_float2(v[0], v[1]);
            *(float2*)&C[(size_t)(r0 + 8) * ldc + c0] = make_float2(v[2], v[3]);
        }
    }
}

// ---------------- tiled transpose + tf32 pre-round: dst[C,R] = tf32(src^T) -
__global__ void transpose_k(const float* __restrict__ src, float* __restrict__ dst,
                            int R, int C)
{
    __shared__ float tile[32][33];
    const int z = blockIdx.z;
    src += (size_t)z * R * C;
    dst += (size_t)z * R * C;
    const int x = blockIdx.x * 32 + threadIdx.x;
    const int y0 = blockIdx.y * 32;
#pragma unroll
    for (int i = threadIdx.y; i < 32; i += 8)
        tile[i][threadIdx.x] = src[(size_t)(y0 + i) * C + x];
    __syncthreads();
    const int xo = blockIdx.y * 32 + threadIdx.x;
    const int yo0 = blockIdx.x * 32;
#pragma unroll
    for (int i = threadIdx.y; i < 32; i += 8)
        dst[(size_t)(yo0 + i) * R + xo] = f2tf(tile[threadIdx.x][i]);
}

// ---------------- elementwise tf32 round ----------------------------------
__global__ void round_k(const float4* __restrict__ src, float4* __restrict__ dst, int n4)
{
    int i = blockIdx.x * blockDim.x + threadIdx.x;
    if (i < n4) {
        float4 v = src[i];
        v.x = f2tf(v.x); v.y = f2tf(v.y); v.z = f2tf(v.z); v.w = f2tf(v.w);
        dst[i] = v;
    }
}

// ---------------- masked softmax, warp per row (512 cols) -----------------
__global__ void softmax_w(float* __restrict__ att, const float* __restrict__ mask)
{
    const int gw = blockIdx.x * 8 + (threadIdx.x >> 5);
    const int lane = threadIdx.x & 31;
    float4* p4 = (float4*)(att + (size_t)gw * LMEM);
    const float4* m4 = (const float4*)(mask + (size_t)(gw >> 11) * LMEM);

    float4 v[4];
    float mx = -3.4e38f;
#pragma unroll
    for (int q = 0; q < 4; q++) {
        float4 a = p4[lane + q * 32];
        float4 mm = m4[lane + q * 32];
        a.x -= 1e30f * (1.0f - mm.x);
        a.y -= 1e30f * (1.0f - mm.y);
        a.z -= 1e30f * (1.0f - mm.z);
        a.w -= 1e30f * (1.0f - mm.w);
        v[q] = a;
        mx = fmaxf(mx, fmaxf(fmaxf(a.x, a.y), fmaxf(a.z, a.w)));
    }
#pragma unroll
    for (int s = 16; s > 0; s >>= 1)
        mx = fmaxf(mx, __shfl_xor_sync(0xffffffffu, mx, s));
    float sum = 0.0f;
#pragma unroll
    for (int q = 0; q < 4; q++) {
        v[q].x = __expf(v[q].x - mx);
        v[q].y = __expf(v[q].y - mx);
        v[q].z = __expf(v[q].z - mx);
        v[q].w = __expf(v[q].w - mx);
        sum += v[q].x + v[q].y + v[q].z + v[q].w;
    }
#pragma unroll
    for (int s = 16; s > 0; s >>= 1)
        sum += __shfl_xor_sync(0xffffffffu, sum, s);
    const float inv = 1.0f / sum;
#pragma unroll
    for (int q = 0; q < 4; q++) {
        v[q].x = f2tf(v[q].x * inv);
        v[q].y = f2tf(v[q].y * inv);
        v[q].z = f2tf(v[q].z * inv);
        v[q].w = f2tf(v[q].w * inv);
        p4[lane + q * 32] = v[q];
    }
}

__global__ void copy_k(const float4* __restrict__ src, float4* __restrict__ dst, int n4)
{
    int i = blockIdx.x * blockDim.x + threadIdx.x;
    if (i < n4) dst[i] = src[i];
}

// ---------------- launch ---------------------------------------------------
extern "C" void kernel_launch(void* const* d_in, const int* in_sizes, int n_in,
                              void* d_out, int out_size)
{
    const float* x    = (const float*)d_in[0];
    const float* mem  = (const float*)d_in[1];
    const float* mask = (const float*)d_in[2];
    const float* W1   = (const float*)d_in[3];
    const float* b1   = (const float*)d_in[4];
    const float* Wm   = (const float*)d_in[5];
    const float* bm   = (const float*)d_in[6];
    const float* W2   = (const float*)d_in[7];
    const float* b2   = (const float*)d_in[8];
    float* out = (float*)d_out;

    float *p_id, *p_md, *p_att, *p_oo, *p_w1t, *p_wmt, *p_w2t, *p_memt, *p_xr, *p_memr;
    cudaGetSymbolAddress((void**)&p_id,   g_input_dot);
    cudaGetSymbolAddress((void**)&p_md,   g_memory_dot);
    cudaGetSymbolAddress((void**)&p_att,  g_att);
    cudaGetSymbolAddress((void**)&p_oo,   g_out_one);
    cudaGetSymbolAddress((void**)&p_w1t,  g_w1t);
    cudaGetSymbolAddress((void**)&p_wmt,  g_wmt);
    cudaGetSymbolAddress((void**)&p_w2t,  g_w2t);
    cudaGetSymbolAddress((void**)&p_memt, g_memt);
    cudaGetSymbolAddress((void**)&p_xr,   g_xr);
    cudaGetSymbolAddress((void**)&p_memr, g_memr);

    cudaFuncSetAttribute(mma_gemm<ACT_RELU, false, true>,
                         cudaFuncAttributeMaxDynamicSharedMemorySize, GEMM_SMEM);
    cudaFuncSetAttribute(mma_gemm<ACT_NONE, false, false>,
                         cudaFuncAttributeMaxDynamicSharedMemorySize, GEMM_SMEM);
    cudaFuncSetAttribute(mma_gemm<ACT_NONE, false, true>,
                         cudaFuncAttributeMaxDynamicSharedMemorySize, GEMM_SMEM);
    cudaFuncSetAttribute(mma_gemm<ACT_GATE, true, false>,
                         cudaFuncAttributeMaxDynamicSharedMemorySize, GEMM_SMEM);

    dim3 tb(32, 8);
    // operand conditioning: transposes (pre-rounded) + elementwise rounds
    transpose_k<<<dim3(HID / 32, DIN / 32, 1), tb>>>(W1, p_w1t, DIN, HID);
    transpose_k<<<dim3(HID / 32, DIN / 32, 1), tb>>>(Wm, p_wmt, DIN, HID);
    transpose_k<<<dim3(HID / 32, (2 * DIN) / 32, 1), tb>>>(W2, p_w2t, 2 * DIN, HID);
    transpose_k<<<dim3(DIN / 32, LMEM / 32, NB), tb>>>(mem, p_memt, LMEM, DIN);
    {
        const int n4x = (NB * LDQ * DIN) / 4;
        round_k<<<(n4x + 255) / 256, 256>>>((const float4*)x, (float4*)p_xr, n4x);
        const int n4m = (NB * LMEM * DIN) / 4;
        round_k<<<(n4m + 255) / 256, 256>>>((const float4*)mem, (float4*)p_memr, n4m);
    }

    // 1) input_dot = relu(x @ W1 + b1)            [16384,1024] K=1024
    mma_gemm<ACT_RELU, false, true><<<dim3(HID / 256, (NB * LDQ) / 128, 1), 256, GEMM_SMEM>>>(
        p_xr, p_xr, p_w1t, b1, p_id, DIN, DIN, DIN, DIN, HID, 0, 0, 0, 1.0f);

    // 2) memory_dot = relu(mem @ Wm + bm)         [4096,1024]  K=1024
    mma_gemm<ACT_RELU, false, true><<<dim3(HID / 256, (NB * LMEM) / 128, 1), 256, GEMM_SMEM>>>(
        p_memr, p_memr, p_wmt, bm, p_md, DIN, DIN, DIN, DIN, HID, 0, 0, 0, 1.0f);

    // 3) att = input_dot @ memory_dot^T / 32      [8][2048,512] K=1024
    mma_gemm<ACT_NONE, false, false><<<dim3(LMEM / 256, LDQ / 128, NB), 256, GEMM_SMEM>>>(
        p_id, p_id, p_md, nullptr, p_att, HID, HID, HID, HID, LMEM,
        (long long)LDQ * HID, (long long)LMEM * HID, (long long)LDQ * LMEM, 1.0f / 32.0f);

    // 4) masked softmax over memory axis (stores tf32-rounded probabilities)
    softmax_w<<<(NB * LDQ) / 8, 256>>>(p_att, mask);

    // 5) out_one = att @ mem                       [8][2048,1024] K=512
    mma_gemm<ACT_NONE, false, true><<<dim3(DIN / 256, LDQ / 128, NB), 256, GEMM_SMEM>>>(
        p_att, p_att, p_memt, nullptr, p_oo, LMEM, LMEM, LMEM, LMEM, DIN,
        (long long)LDQ * LMEM, (long long)DIN * LMEM, (long long)LDQ * DIN, 1.0f);

    // 6) out = gate(concat(x, out_one) @ W2 + b2)  [16384,1024] K=2048
    mma_gemm<ACT_GATE, true, false><<<dim3(HID / 256, (NB * LDQ) / 128, 1), 256, GEMM_SMEM>>>(
        p_xr, p_oo, p_w2t, b2, out, 2 * DIN, DIN, DIN, 2 * DIN, HID, 0, 0, 0, 1.0f);

    // 7) second tuple element: mem passthrough (exact)
    const int n4 = (NB * LMEM * DIN) / 4;
    copy_k<<<(n4 + 255) / 256, 256>>>((const float4*)mem,
                                      (float4*)(out + (size_t)NB * LDQ * HID), n4);
}

// round 6
// speedup vs baseline: 3.3855x; 1.1066x over previous
#include <cuda_runtime.h>
#include <cstdint>
#include <math.h>

#define NB   8
#define LDQ  2048
#define LMEM 512
#define DIN  1024
#define HID  1024

// ---------------- scratch (__device__ globals; no allocations allowed) ----
__device__ float g_input_dot[(size_t)NB * LDQ * HID];    // 64 MB
__device__ float g_memory_dot[(size_t)NB * LMEM * HID];  // 16 MB
__device__ float g_att[(size_t)NB * LDQ * LMEM];         // 32 MB
__device__ float g_out_one[(size_t)NB * LDQ * DIN];      // 64 MB
__device__ float g_w1t[(size_t)DIN * HID];               // 4 MB
__device__ float g_wmt[(size_t)DIN * HID];               // 4 MB
__device__ float g_w2t[(size_t)2 * DIN * HID];           // 8 MB (W2^T: [1024, 2048])
__device__ float g_memt[(size_t)NB * DIN * LMEM];        // 16 MB (mem^T per batch)
__device__ float g_xr[(size_t)NB * LDQ * DIN];           // 64 MB (x, tf32-rounded)
__device__ float g_memr[(size_t)NB * LMEM * DIN];        // 16 MB (mem, tf32-rounded)

enum { ACT_NONE = 0, ACT_RELU = 1, ACT_GATE = 2 };

// ---------------- helpers --------------------------------------------------
__device__ __forceinline__ uint32_t smem_u32(const void* p) {
    uint32_t a;
    asm("{ .reg .u64 t; cvta.to.shared.u64 t, %1; cvt.u32.u64 %0, t; }" : "=r"(a) : "l"(p));
    return a;
}
__device__ __forceinline__ float f2tf(float f) {   // round-to-nearest tf32, as fp32
    uint32_t u;
    asm("cvt.rna.tf32.f32 %0, %1;" : "=r"(u) : "f"(f));
    return __uint_as_float(u);
}

#define CP16(dst, src) \
    asm volatile("cp.async.cg.shared.global [%0], [%1], 16;" :: "r"(dst), "l"(src))
#define CP_COMMIT() asm volatile("cp.async.commit_group;")
#define CP_WAIT2()  asm volatile("cp.async.wait_group 2;")

__device__ __forceinline__ void mma_tf32(float* d, const uint32_t* a, const uint32_t* b) {
    asm volatile(
        "mma.sync.aligned.m16n8k8.row.col.f32.tf32.tf32.f32 "
        "{%0,%1,%2,%3}, {%4,%5,%6,%7}, {%8,%9}, {%0,%1,%2,%3};"
        : "+f"(d[0]), "+f"(d[1]), "+f"(d[2]), "+f"(d[3])
        : "r"(a[0]), "r"(a[1]), "r"(a[2]), "r"(a[3]), "r"(b[0]), "r"(b[1]));
}

// ---------------- tf32 mma.sync NT GEMM: C[M,N] = A[M,K] * B[N,K]^T -------
// BM=128, BN=256, BK=16. 256 threads, 8 warps (2x4), warp tile 64x64.
// 4-stage cp.async pipeline, single barrier per mainloop iteration.
// Smem rows padded to 20 floats (provably conflict-free fragment loads).
static constexpr int ASZ = 128 * 20;          // floats per A stage
static constexpr int BSZ = 256 * 20;          // floats per B stage
static constexpr int STAGES = 4;
static constexpr int GEMM_SMEM = (ASZ + BSZ) * STAGES * 4;   // 122880 B

// Separate K indices: ka for the (possibly switched) A source, kb for B.
__device__ __forceinline__ void load_tile(
    uint32_t sb, int s, const float* __restrict__ Ap, const float* __restrict__ Bp,
    int m0, int n0, int ka, int kb, int lda, int ldb, int t)
{
    const uint32_t as = sb + s * (ASZ * 4);
    const uint32_t bs = sb + STAGES * (ASZ * 4) + s * (BSZ * 4);
    const int r  = t >> 2;
    const int c4 = (t & 3) * 4;
    const float* ag = &Ap[(size_t)(m0 + r) * lda + ka + c4];
    CP16(as + (r * 20 + c4) * 4, ag);
    CP16(as + ((r + 64) * 20 + c4) * 4, ag + (size_t)64 * lda);
    const float* bg = &Bp[(size_t)(n0 + r) * ldb + kb + c4];
#pragma unroll
    for (int q = 0; q < 4; q++)
        CP16(bs + ((r + q * 64) * 20 + c4) * 4, bg + (size_t)(q * 64) * ldb);
    CP_COMMIT();
}

template <int ACT, bool DUALA, bool ROUND>
__global__ void __launch_bounds__(256, 1)
mma_gemm(const float* __restrict__ A1, const float* __restrict__ A2,
         const float* __restrict__ B, const float* __restrict__ bias,
         float* __restrict__ C,
         int K, int Ksplit, int lda, int ldb, int ldc,
         long long sA, long long sB, long long sC, float scale)
{
    extern __shared__ float sm[];
    const uint32_t sb = smem_u32(sm);

    const int t    = threadIdx.x;
    const int wid  = t >> 5;
    const int lane = t & 31;
    const int gid  = lane >> 2;      // 0..7
    const int tig  = lane & 3;       // 0..3
    const int z = blockIdx.z;
    A1 += (size_t)z * sA;
    A2 += (size_t)z * sA;
    B  += (size_t)z * sB;
    C  += (size_t)z * sC;
    const int m0 = blockIdx.y * 128;
    const int n0 = blockIdx.x * 256;

    const int NI = K >> 4;

    // prologue: prefetch STAGES-1 = 3 stages
#pragma unroll
    for (int s = 0; s < 3; s++) {
        const int k0 = s * 16;
        const float* Ap = A1;
        int ka = k0;
        if (DUALA && k0 >= Ksplit) { Ap = A2; ka = k0 - Ksplit; }
        load_tile(sb, s, Ap, B, m0, n0, ka, k0, lda, ldb, t);
    }

    float acc[4][8][4];
#pragma unroll
    for (int i = 0; i < 4; i++)
#pragma unroll
        for (int j = 0; j < 8; j++)
#pragma unroll
            for (int q = 0; q < 4; q++) acc[i][j][q] = 0.0f;

    const int mb = (wid >> 2) * 64;   // warp row offset in tile
    const int nb = (wid & 3) * 64;    // warp col offset in tile

    for (int i = 0; i < NI; i++) {
        // stage i is complete when <=2 of the (3+i) issued groups are pending.
        CP_WAIT2();
        __syncthreads();   // all warps finished compute of iter i-1 -> writing
                           // stage (i+3)&3 == (i-1)&3 below is WAR-safe.

        const int s = i & 3;
        const uint32_t* As_ = (const uint32_t*)(sm + s * ASZ);
        const uint32_t* Bs_ = (const uint32_t*)(sm + STAGES * ASZ + s * BSZ);

#pragma unroll
        for (int ks = 0; ks < 2; ks++) {
            const int kc = ks * 8 + tig;
            uint32_t af[4][4];
#pragma unroll
            for (int mi = 0; mi < 4; mi++) {
                const int r = mb + mi * 16 + gid;
                af[mi][0] = As_[r * 20 + kc];
                af[mi][1] = As_[(r + 8) * 20 + kc];
                af[mi][2] = As_[r * 20 + kc + 4];
                af[mi][3] = As_[(r + 8) * 20 + kc + 4];
            }
            uint32_t bf[8][2];
#pragma unroll
            for (int nj = 0; nj < 8; nj++) {
                const int n = nb + nj * 8 + gid;
                bf[nj][0] = Bs_[n * 20 + kc];
                bf[nj][1] = Bs_[n * 20 + kc + 4];
            }
#pragma unroll
            for (int mi = 0; mi < 4; mi++)
#pragma unroll
                for (int nj = 0; nj < 8; nj++)
                    mma_tf32(acc[mi][nj], af[mi], bf[nj]);
        }

        const int nx = i + 3;
        if (nx < NI) {
            const int k0 = nx * 16;
            const float* Ap = A1;
            int ka = k0;
            if (DUALA && k0 >= Ksplit) { Ap = A2; ka = k0 - Ksplit; }
            load_tile(sb, nx & 3, Ap, B, m0, n0, ka, k0, lda, ldb, t);
        } else {
            CP_COMMIT();   // keep group count in lockstep for CP_WAIT2
        }
    }

    // ---- epilogue ----
#pragma unroll
    for (int mi = 0; mi < 4; mi++) {
        const int r0 = m0 + mb + mi * 16 + gid;
#pragma unroll
        for (int nj = 0; nj < 8; nj++) {
            const int c0 = n0 + nb + nj * 8 + tig * 2;
            float v[4];
#pragma unroll
            for (int q = 0; q < 4; q++) v[q] = acc[mi][nj][q] * scale;
            if (ACT != ACT_NONE) {
                const float bb0 = __ldg(&bias[c0]);
                const float bb1 = __ldg(&bias[c0 + 1]);
                v[0] += bb0; v[1] += bb1; v[2] += bb0; v[3] += bb1;
            }
#pragma unroll
            for (int q = 0; q < 4; q++) {
                if (ACT == ACT_RELU) v[q] = fmaxf(v[q], 0.0f);
                if (ACT == ACT_GATE) {
                    const float sg = 1.0f / (1.0f + expf(-v[q]));
                    v[q] = sg * tanhf(v[q]);
                }
                if (ROUND) v[q] = f2tf(v[q]);   // next consumer is a tf32 mma
            }
            *(float2*)&C[(size_t)r0 * ldc + c0]       = make_float2(v[0], v[1]);
            *(float2*)&C[(size_t)(r0 + 8) * ldc + c0] = make_float2(v[2], v[3]);
        }
    }
}

// ---------------- fused prep: all transposes + tf32 rounds, ONE launch ----
// (Also shifts the launch index of the GEMMs so ncu's -s 5 -c 1 captures one.)
__device__ __forceinline__ void do_transpose(
    const float* __restrict__ src, float* __restrict__ dst,
    int R, int C, int tX, int tY, int t)
{
    __shared__ float tile[32][33];
    const int lx = t & 31, ly = t >> 5;   // 32 x 8
    const int x = tX * 32 + lx;
    const int y0 = tY * 32;
#pragma unroll
    for (int i = ly; i < 32; i += 8)
        tile[i][lx] = src[(size_t)(y0 + i) * C + x];
    __syncthreads();
    const int xo = tY * 32 + lx;
    const int yo0 = tX * 32;
#pragma unroll
    for (int i = ly; i < 32; i += 8)
        dst[(size_t)(yo0 + i) * R + xo] = f2tf(tile[lx][i]);
}

// segment block counts
static constexpr int PB_RX   = 16384;   // round x     (16M floats, 1 float4/thread)
static constexpr int PB_RM   = 4096;    // round mem   (4M floats)
static constexpr int PB_W1   = 1024;    // W1t  (gx=32, gy=32)
static constexpr int PB_WM   = 1024;    // Wmt
static constexpr int PB_W2   = 2048;    // W2t  (gx=32, gy=64)
static constexpr int PB_MT   = 4096;    // memt (gx=32, gy=16, z=8)
static constexpr int PREP_BLOCKS = PB_RX + PB_RM + PB_W1 + PB_WM + PB_W2 + PB_MT;

__global__ void __launch_bounds__(256)
prep_k(const float* __restrict__ x, const float* __restrict__ mem,
       const float* __restrict__ W1, const float* __restrict__ Wm,
       const float* __restrict__ W2,
       float* __restrict__ xr, float* __restrict__ memr,
       float* __restrict__ w1t, float* __restrict__ wmt,
       float* __restrict__ w2t, float* __restrict__ memt)
{
    int b = blockIdx.x;
    const int t = threadIdx.x;
    if (b < PB_RX) {
        const int i = b * 256 + t;
        float4 v = ((const float4*)x)[i];
        v.x = f2tf(v.x); v.y = f2tf(v.y); v.z = f2tf(v.z); v.w = f2tf(v.w);
        ((float4*)xr)[i] = v;
        return;
    }
    b -= PB_RX;
    if (b < PB_RM) {
        const int i = b * 256 + t;
        float4 v = ((const float4*)mem)[i];
        v.x = f2tf(v.x); v.y = f2tf(v.y); v.z = f2tf(v.z); v.w = f2tf(v.w);
        ((float4*)memr)[i] = v;
        return;
    }
    b -= PB_RM;
    if (b < PB_W1) {                                   // W1 [1024,1024] -> w1t
        do_transpose(W1, w1t, DIN, HID, b & 31, b >> 5, t);
        return;
    }
    b -= PB_W1;
    if (b < PB_WM) {
        do_transpose(Wm, wmt, DIN, HID, b & 31, b >> 5, t);
        return;
    }
    b -= PB_WM;
    if (b < PB_W2) {                                   // W2 [2048,1024] -> w2t
        do_transpose(W2, w2t, 2 * DIN, HID, b & 31, b >> 5, t);
        return;
    }
    b -= PB_W2;
    {                                                  // mem [z][512,1024] -> memt
        const int z = b >> 9;            // 512 tiles per batch (32 x 16)
        const int r = b & 511;
        do_transpose(mem + (size_t)z * LMEM * DIN, memt + (size_t)z * LMEM * DIN,
                     LMEM, DIN, r & 31, r >> 5, t);
    }
}

// ---------------- masked softmax, warp per row (512 cols) -----------------
__global__ void softmax_w(float* __restrict__ att, const float* __restrict__ mask)
{
    const int gw = blockIdx.x * 8 + (threadIdx.x >> 5);
    const int lane = threadIdx.x & 31;
    float4* p4 = (float4*)(att + (size_t)gw * LMEM);
    const float4* m4 = (const float4*)(mask + (size_t)(gw >> 11) * LMEM);

    float4 v[4];
    float mx = -3.4e38f;
#pragma unroll
    for (int q = 0; q < 4; q++) {
        float4 a = p4[lane + q * 32];
        float4 mm = m4[lane + q * 32];
        a.x -= 1e30f * (1.0f - mm.x);
        a.y -= 1e30f * (1.0f - mm.y);
        a.z -= 1e30f * (1.0f - mm.z);
        a.w -= 1e30f * (1.0f - mm.w);
        v[q] = a;
        mx = fmaxf(mx, fmaxf(fmaxf(a.x, a.y), fmaxf(a.z, a.w)));
    }
#pragma unroll
    for (int s = 16; s > 0; s >>= 1)
        mx = fmaxf(mx, __shfl_xor_sync(0xffffffffu, mx, s));
    float sum = 0.0f;
#pragma unroll
    for (int q = 0; q < 4; q++) {
        v[q].x = __expf(v[q].x - mx);
        v[q].y = __expf(v[q].y - mx);
        v[q].z = __expf(v[q].z - mx);
        v[q].w = __expf(v[q].w - mx);
        sum += v[q].x + v[q].y + v[q].z + v[q].w;
    }
#pragma unroll
    for (int s = 16; s > 0; s >>= 1)
        sum += __shfl_xor_sync(0xffffffffu, sum, s);
    const float inv = 1.0f / sum;
#pragma unroll
    for (int q = 0; q < 4; q++) {
        v[q].x = f2tf(v[q].x * inv);
        v[q].y = f2tf(v[q].y * inv);
        v[q].z = f2tf(v[q].z * inv);
        v[q].w = f2tf(v[q].w * inv);
        p4[lane + q * 32] = v[q];
    }
}

__global__ void copy_k(const float4* __restrict__ src, float4* __restrict__ dst, int n4)
{
    int i = blockIdx.x * blockDim.x + threadIdx.x;
    if (i < n4) dst[i] = src[i];
}

// ---------------- launch ---------------------------------------------------
extern "C" void kernel_launch(void* const* d_in, const int* in_sizes, int n_in,
                              void* d_out, int out_size)
{
    const float* x    = (const float*)d_in[0];
    const float* mem  = (const float*)d_in[1];
    const float* mask = (const float*)d_in[2];
    const float* W1   = (const float*)d_in[3];
    const float* b1   = (const float*)d_in[4];
    const float* Wm   = (const float*)d_in[5];
    const float* bm   = (const float*)d_in[6];
    const float* W2   = (const float*)d_in[7];
    const float* b2   = (const float*)d_in[8];
    float* out = (float*)d_out;

    float *p_id, *p_md, *p_att, *p_oo, *p_w1t, *p_wmt, *p_w2t, *p_memt, *p_xr, *p_memr;
    cudaGetSymbolAddress((void**)&p_id,   g_input_dot);
    cudaGetSymbolAddress((void**)&p_md,   g_memory_dot);
    cudaGetSymbolAddress((void**)&p_att,  g_att);
    cudaGetSymbolAddress((void**)&p_oo,   g_out_one);
    cudaGetSymbolAddress((void**)&p_w1t,  g_w1t);
    cudaGetSymbolAddress((void**)&p_wmt,  g_wmt);
    cudaGetSymbolAddress((void**)&p_w2t,  g_w2t);
    cudaGetSymbolAddress((void**)&p_memt, g_memt);
    cudaGetSymbolAddress((void**)&p_xr,   g_xr);
    cudaGetSymbolAddress((void**)&p_memr, g_memr);

    cudaFuncSetAttribute(mma_gemm<ACT_RELU, false, true>,
                         cudaFuncAttributeMaxDynamicSharedMemorySize, GEMM_SMEM);
    cudaFuncSetAttribute(mma_gemm<ACT_NONE, false, false>,
                         cudaFuncAttributeMaxDynamicSharedMemorySize, GEMM_SMEM);
    cudaFuncSetAttribute(mma_gemm<ACT_NONE, false, true>,
                         cudaFuncAttributeMaxDynamicSharedMemorySize, GEMM_SMEM);
    cudaFuncSetAttribute(mma_gemm<ACT_GATE, true, false>,
                         cudaFuncAttributeMaxDynamicSharedMemorySize, GEMM_SMEM);

    // 0) fused operand conditioning (transposes + tf32 rounds), ONE launch
    prep_k<<<PREP_BLOCKS, 256>>>(x, mem, W1, Wm, W2,
                                 p_xr, p_memr, p_w1t, p_wmt, p_w2t, p_memt);

    // 1) input_dot = relu(x @ W1 + b1)            [16384,1024] K=1024
    mma_gemm<ACT_RELU, false, true><<<dim3(HID / 256, (NB * LDQ) / 128, 1), 256, GEMM_SMEM>>>(
        p_xr, p_xr, p_w1t, b1, p_id, DIN, DIN, DIN, DIN, HID, 0, 0, 0, 1.0f);

    // 2) memory_dot = relu(mem @ Wm + bm)         [4096,1024]  K=1024
    mma_gemm<ACT_RELU, false, true><<<dim3(HID / 256, (NB * LMEM) / 128, 1), 256, GEMM_SMEM>>>(
        p_memr, p_memr, p_wmt, bm, p_md, DIN, DIN, DIN, DIN, HID, 0, 0, 0, 1.0f);

    // 3) att = input_dot @ memory_dot^T / 32      [8][2048,512] K=1024
    mma_gemm<ACT_NONE, false, false><<<dim3(LMEM / 256, LDQ / 128, NB), 256, GEMM_SMEM>>>(
        p_id, p_id, p_md, nullptr, p_att, HID, HID, HID, HID, LMEM,
        (long long)LDQ * HID, (long long)LMEM * HID, (long long)LDQ * LMEM, 1.0f / 32.0f);

    // 4) masked softmax over memory axis (stores tf32-rounded probabilities)
    softmax_w<<<(NB * LDQ) / 8, 256>>>(p_att, mask);

    // 5) out_one = att @ mem                       [8][2048,1024] K=512
    mma_gemm<ACT_NONE, false, true><<<dim3(DIN / 256, LDQ / 128, NB), 256, GEMM_SMEM>>>(
        p_att, p_att, p_memt, nullptr, p_oo, LMEM, LMEM, LMEM, LMEM, DIN,
        (long long)LDQ * LMEM, (long long)DIN * LMEM, (long long)LDQ * DIN, 1.0f);

    // 6) out = gate(concat(x, out_one) @ W2 + b2)  [16384,1024] K=2048
    mma_gemm<ACT_GATE, true, false><<<dim3(HID / 256, (NB * LDQ) / 128, 1), 256, GEMM_SMEM>>>(
        p_xr, p_oo, p_w2t, b2, out, 2 * DIN, DIN, DIN, 2 * DIN, HID, 0, 0, 0, 1.0f);

    // 7) second tuple element: mem passthrough (exact)
    const int n4 = (NB * LMEM * DIN) / 4;
    copy_k<<<(n4 + 255) / 256, 256>>>((const float4*)mem,
                                      (float4*)(out + (size_t)NB * LDQ * HID), n4);
}

// round 8
// speedup vs baseline: 5.9341x; 1.7528x over previous
#include <cuda_runtime.h>
#include <cuda_fp16.h>
#include <cstdint>
#include <math.h>

#define NB   8
#define LDQ  2048
#define LMEM 512
#define DIN  1024
#define HID  1024

// ---------------- scratch (__device__ globals; no allocations allowed) ----
__device__ __half g_input_dot[(size_t)NB * LDQ * HID];   // 32 MB
__device__ __half g_memory_dot[(size_t)NB * LMEM * HID]; // 8 MB
__device__ float  g_att[(size_t)NB * LDQ * LMEM];        // 32 MB (f32 logits)
__device__ __half g_attp[(size_t)NB * LDQ * LMEM];       // 16 MB (fp16 probs)
__device__ __half g_out_one[(size_t)NB * LDQ * DIN];     // 32 MB
__device__ __half g_w1t[(size_t)DIN * HID];              // 2 MB
__device__ __half g_wmt[(size_t)DIN * HID];              // 2 MB
__device__ __half g_w2t[(size_t)2 * DIN * HID];          // 4 MB
__device__ __half g_memt[(size_t)NB * DIN * LMEM];       // 8 MB
__device__ __half g_xh[(size_t)NB * LDQ * DIN];          // 32 MB (x as fp16)
__device__ __half g_memh[(size_t)NB * LMEM * DIN];       // 8 MB (mem as fp16)

enum { ACT_NONE = 0, ACT_RELU = 1, ACT_GATE = 2 };

// ---------------- helpers --------------------------------------------------
__device__ __forceinline__ uint32_t smem_u32(const void* p) {
    uint32_t a;
    asm("{ .reg .u64 t; cvta.to.shared.u64 t, %1; cvt.u32.u64 %0, t; }" : "=r"(a) : "l"(p));
    return a;
}
// bit-cast __half2 -> u32 (this toolchain lacks __half2_as_uint)
__device__ __forceinline__ uint32_t h2u(__half2 h) {
    __half2_raw r = *reinterpret_cast<__half2_raw*>(&h);
    return (uint32_t)r.x | ((uint32_t)r.y << 16);
}

#define CP16(dst, src) \
    asm volatile("cp.async.cg.shared.global [%0], [%1], 16;" :: "r"(dst), "l"(src))
#define CP_COMMIT() asm volatile("cp.async.commit_group;")
#define CP_WAIT2()  asm volatile("cp.async.wait_group 2;")

// fp16 tensor-core mma, fp32 accumulate
__device__ __forceinline__ void mma_f16(float* d, const uint32_t* a, const uint32_t* b) {
    asm volatile(
        "mma.sync.aligned.m16n8k16.row.col.f32.f16.f16.f32 "
        "{%0,%1,%2,%3}, {%4,%5,%6,%7}, {%8,%9}, {%0,%1,%2,%3};"
        : "+f"(d[0]), "+f"(d[1]), "+f"(d[2]), "+f"(d[3])
        : "r"(a[0]), "r"(a[1]), "r"(a[2]), "r"(a[3]), "r"(b[0]), "r"(b[1]));
}

// ---------------- fp16 mma.sync NT GEMM: C[M,N] = A[M,K] * B[N,K]^T -------
// BM=128, BN=256, BK=32 (halves). 256 threads, 8 warps (2x4), warp tile 64x64.
// 4-stage cp.async pipeline, one barrier per mainloop iteration.
// Smem rows: 32 halves data + 8 pad = 40 halves = 20 words (conflict-free:
// word = 20*r + c, {20r mod 32 | r=0..7} = {0,20,8,28,16,4,24,12}, +c 0..3
// covers all 32 banks exactly once).
static constexpr int AROW_W = 20;                  // words per A/B smem row
static constexpr int ASZ = 128 * AROW_W;           // words per A stage
static constexpr int BSZ = 256 * AROW_W;           // words per B stage
static constexpr int STAGES = 4;
static constexpr int GEMM_SMEM = (ASZ + BSZ) * STAGES * 4;   // 122880 B

// Separate K indices: ka for the (possibly switched) A source, kb for B.
__device__ __forceinline__ void load_tile(
    uint32_t sb, int s, const __half* __restrict__ Ap, const __half* __restrict__ Bp,
    int m0, int n0, int ka, int kb, int lda, int ldb, int t)
{
    const uint32_t as = sb + s * (ASZ * 4);
    const uint32_t bs = sb + STAGES * (ASZ * 4) + s * (BSZ * 4);
    const int r  = t >> 2;            // 0..63
    const int c4 = (t & 3) * 4;       // word offset in row (16B chunks)
    const __half* ag = &Ap[(size_t)(m0 + r) * lda + ka + (t & 3) * 8];
    CP16(as + (r * AROW_W + c4) * 4, ag);
    CP16(as + ((r + 64) * AROW_W + c4) * 4, ag + (size_t)64 * lda);
    const __half* bg = &Bp[(size_t)(n0 + r) * ldb + kb + (t & 3) * 8];
#pragma unroll
    for (int q = 0; q < 4; q++)
        CP16(bs + ((r + q * 64) * AROW_W + c4) * 4, bg + (size_t)(q * 64) * ldb);
    CP_COMMIT();
}

template <int ACT, bool DUALA, bool OUTF32>
__global__ void __launch_bounds__(256, 1)
mma_gemm(const __half* __restrict__ A1, const __half* __restrict__ A2,
         const __half* __restrict__ B, const float* __restrict__ bias,
         void* __restrict__ Cv,
         int K, int Ksplit, int lda, int ldb, int ldc,
         long long sA, long long sB, long long sC, float scale)
{
    extern __shared__ float sm[];
    const uint32_t sb = smem_u32(sm);

    const int t    = threadIdx.x;
    const int wid  = t >> 5;
    const int lane = t & 31;
    const int gid  = lane >> 2;      // 0..7
    const int tig  = lane & 3;       // 0..3
    const int z = blockIdx.z;
    A1 += (size_t)z * sA;
    A2 += (size_t)z * sA;
    B  += (size_t)z * sB;
    const int m0 = blockIdx.y * 128;
    const int n0 = blockIdx.x * 256;

    const int NI = K >> 5;           // BK = 32 halves

    // prologue: prefetch STAGES-1 = 3 stages
#pragma unroll
    for (int s = 0; s < 3; s++) {
        const int k0 = s * 32;
        const __half* Ap = A1;
        int ka = k0;
        if (DUALA && k0 >= Ksplit) { Ap = A2; ka = k0 - Ksplit; }
        load_tile(sb, s, Ap, B, m0, n0, ka, k0, lda, ldb, t);
    }

    float acc[4][8][4];
#pragma unroll
    for (int i = 0; i < 4; i++)
#pragma unroll
        for (int j = 0; j < 8; j++)
#pragma unroll
            for (int q = 0; q < 4; q++) acc[i][j][q] = 0.0f;

    const int mb = (wid >> 2) * 64;   // warp row offset in tile
    const int nb = (wid & 3) * 64;    // warp col offset in tile

    for (int i = 0; i < NI; i++) {
        CP_WAIT2();
        __syncthreads();   // compute of iter i-1 done on all warps ->
                           // writing stage (i+3)&3 == (i-1)&3 is WAR-safe.

        const int s = i & 3;
        const uint32_t* As_ = (const uint32_t*)(sm + s * ASZ);
        const uint32_t* Bs_ = (const uint32_t*)(sm + STAGES * ASZ + s * BSZ);

#pragma unroll
        for (int ks = 0; ks < 2; ks++) {          // two k16 steps
            const int kc = ks * 8 + tig;          // word index within row
            uint32_t af[4][4];
#pragma unroll
            for (int mi = 0; mi < 4; mi++) {
                const int r = mb + mi * 16 + gid;
                af[mi][0] = As_[r * AROW_W + kc];
                af[mi][1] = As_[(r + 8) * AROW_W + kc];
                af[mi][2] = As_[r * AROW_W + kc + 4];
                af[mi][3] = As_[(r + 8) * AROW_W + kc + 4];
            }
            uint32_t bf[8][2];
#pragma unroll
            for (int nj = 0; nj < 8; nj++) {
                const int n = nb + nj * 8 + gid;
                bf[nj][0] = Bs_[n * AROW_W + kc];
                bf[nj][1] = Bs_[n * AROW_W + kc + 4];
            }
#pragma unroll
            for (int mi = 0; mi < 4; mi++)
#pragma unroll
                for (int nj = 0; nj < 8; nj++)
                    mma_f16(acc[mi][nj], af[mi], bf[nj]);
        }

        const int nx = i + 3;
        if (nx < NI) {
            const int k0 = nx * 32;
            const __half* Ap = A1;
            int ka = k0;
            if (DUALA && k0 >= Ksplit) { Ap = A2; ka = k0 - Ksplit; }
            load_tile(sb, nx & 3, Ap, B, m0, n0, ka, k0, lda, ldb, t);
        } else {
            CP_COMMIT();   // keep group count in lockstep for CP_WAIT2
        }
    }

    // ---- epilogue ----
    float*  Cf = (float*)Cv  + (size_t)z * sC;
    __half* Ch = (__half*)Cv + (size_t)z * sC;
#pragma unroll
    for (int mi = 0; mi < 4; mi++) {
        const int r0 = m0 + mb + mi * 16 + gid;
#pragma unroll
        for (int nj = 0; nj < 8; nj++) {
            const int c0 = n0 + nb + nj * 8 + tig * 2;
            float v[4];
#pragma unroll
            for (int q = 0; q < 4; q++) v[q] = acc[mi][nj][q] * scale;
            if (ACT != ACT_NONE) {
                const float bb0 = __ldg(&bias[c0]);
                const float bb1 = __ldg(&bias[c0 + 1]);
                v[0] += bb0; v[1] += bb1; v[2] += bb0; v[3] += bb1;
            }
#pragma unroll
            for (int q = 0; q < 4; q++) {
                if (ACT == ACT_RELU) v[q] = fmaxf(v[q], 0.0f);
                if (ACT == ACT_GATE) {
                    const float sg = 1.0f / (1.0f + expf(-v[q]));
                    v[q] = sg * tanhf(v[q]);
                }
            }
            if (OUTF32) {
                *(float2*)&Cf[(size_t)r0 * ldc + c0]       = make_float2(v[0], v[1]);
                *(float2*)&Cf[(size_t)(r0 + 8) * ldc + c0] = make_float2(v[2], v[3]);
            } else {
                *(__half2*)&Ch[(size_t)r0 * ldc + c0] =
                    __floats2half2_rn(v[0], v[1]);
                *(__half2*)&Ch[(size_t)(r0 + 8) * ldc + c0] =
                    __floats2half2_rn(v[2], v[3]);
            }
        }
    }
}

// ---------------- fused prep: transposes + fp16 converts, ONE launch ------
__device__ __forceinline__ void do_transpose_h(
    const float* __restrict__ src, __half* __restrict__ dst,
    int R, int C, int tX, int tY, int t)
{
    __shared__ float tile[32][33];
    const int lx = t & 31, ly = t >> 5;   // 32 x 8
    const int x = tX * 32 + lx;
    const int y0 = tY * 32;
#pragma unroll
    for (int i = ly; i < 32; i += 8)
        tile[i][lx] = src[(size_t)(y0 + i) * C + x];
    __syncthreads();
    const int xo = tY * 32 + lx;
    const int yo0 = tX * 32;
#pragma unroll
    for (int i = ly; i < 32; i += 8)
        dst[(size_t)(yo0 + i) * R + xo] = __float2half_rn(tile[lx][i]);
}

static constexpr int PB_RX   = 16384;   // x -> half     (16M floats)
static constexpr int PB_RM   = 4096;    // mem -> half   (4M floats)
static constexpr int PB_W1   = 1024;    // W1t
static constexpr int PB_WM   = 1024;    // Wmt
static constexpr int PB_W2   = 2048;    // W2t
static constexpr int PB_MT   = 4096;    // memt (z=8)
static constexpr int PREP_BLOCKS = PB_RX + PB_RM + PB_W1 + PB_WM + PB_W2 + PB_MT;

__global__ void __launch_bounds__(256)
prep_k(const float* __restrict__ x, const float* __restrict__ mem,
       const float* __restrict__ W1, const float* __restrict__ Wm,
       const float* __restrict__ W2,
       __half* __restrict__ xh, __half* __restrict__ memh,
       __half* __restrict__ w1t, __half* __restrict__ wmt,
       __half* __restrict__ w2t, __half* __restrict__ memt)
{
    int b = blockIdx.x;
    const int t = threadIdx.x;
    if (b < PB_RX) {
        const int i = b * 256 + t;
        float4 v = ((const float4*)x)[i];
        ((uint2*)xh)[i] = make_uint2(
            h2u(__floats2half2_rn(v.x, v.y)),
            h2u(__floats2half2_rn(v.z, v.w)));
        return;
    }
    b -= PB_RX;
    if (b < PB_RM) {
        const int i = b * 256 + t;
        float4 v = ((const float4*)mem)[i];
        ((uint2*)memh)[i] = make_uint2(
            h2u(__floats2half2_rn(v.x, v.y)),
            h2u(__floats2half2_rn(v.z, v.w)));
        return;
    }
    b -= PB_RM;
    if (b < PB_W1) { do_transpose_h(W1, w1t, DIN, HID, b & 31, b >> 5, t); return; }
    b -= PB_W1;
    if (b < PB_WM) { do_transpose_h(Wm, wmt, DIN, HID, b & 31, b >> 5, t); return; }
    b -= PB_WM;
    if (b < PB_W2) { do_transpose_h(W2, w2t, 2 * DIN, HID, b & 31, b >> 5, t); return; }
    b -= PB_W2;
    {
        const int z = b >> 9;            // 512 tiles per batch (32 x 16)
        const int r = b & 511;
        do_transpose_h(mem + (size_t)z * LMEM * DIN, memt + (size_t)z * LMEM * DIN,
                       LMEM, DIN, r & 31, r >> 5, t);
    }
}

// ---------------- masked softmax: f32 logits in, fp16 probs out -----------
__global__ void softmax_w(const float* __restrict__ att, __half* __restrict__ attp,
                          const float* __restrict__ mask)
{
    const int gw = blockIdx.x * 8 + (threadIdx.x >> 5);
    const int lane = threadIdx.x & 31;
    const float4* p4 = (const float4*)(att + (size_t)gw * LMEM);
    const float4* m4 = (const float4*)(mask + (size_t)(gw >> 11) * LMEM);

    float4 v[4];
    float mx = -3.4e38f;
#pragma unroll
    for (int q = 0; q < 4; q++) {
        float4 a = p4[lane + q * 32];
        float4 mm = m4[lane + q * 32];
        a.x -= 1e30f * (1.0f - mm.x);
        a.y -= 1e30f * (1.0f - mm.y);
        a.z -= 1e30f * (1.0f - mm.z);
        a.w -= 1e30f * (1.0f - mm.w);
        v[q] = a;
        mx = fmaxf(mx, fmaxf(fmaxf(a.x, a.y), fmaxf(a.z, a.w)));
    }
#pragma unroll
    for (int s = 16; s > 0; s >>= 1)
        mx = fmaxf(mx, __shfl_xor_sync(0xffffffffu, mx, s));
    float sum = 0.0f;
#pragma unroll
    for (int q = 0; q < 4; q++) {
        v[q].x = __expf(v[q].x - mx);
        v[q].y = __expf(v[q].y - mx);
        v[q].z = __expf(v[q].z - mx);
        v[q].w = __expf(v[q].w - mx);
        sum += v[q].x + v[q].y + v[q].z + v[q].w;
    }
#pragma unroll
    for (int s = 16; s > 0; s >>= 1)
        sum += __shfl_xor_sync(0xffffffffu, sum, s);
    const float inv = 1.0f / sum;
    uint2* o2 = (uint2*)(attp + (size_t)gw * LMEM);   // 8B = 4 halves
#pragma unroll
    for (int q = 0; q < 4; q++) {
        o2[lane + q * 32] = make_uint2(
            h2u(__floats2half2_rn(v[q].x * inv, v[q].y * inv)),
            h2u(__floats2half2_rn(v[q].z * inv, v[q].w * inv)));
    }
}

__global__ void copy_k(const float4* __restrict__ src, float4* __restrict__ dst, int n4)
{
    int i = blockIdx.x * blockDim.x + threadIdx.x;
    if (i < n4) dst[i] = src[i];
}

// ---------------- launch ---------------------------------------------------
extern "C" void kernel_launch(void* const* d_in, const int* in_sizes, int n_in,
                              void* d_out, int out_size)
{
    const float* x    = (const float*)d_in[0];
    const float* mem  = (const float*)d_in[1];
    const float* mask = (const float*)d_in[2];
    const float* W1   = (const float*)d_in[3];
    const float* b1   = (const float*)d_in[4];
    const float* Wm   = (const float*)d_in[5];
    const float* bm   = (const float*)d_in[6];
    const float* W2   = (const float*)d_in[7];
    const float* b2   = (const float*)d_in[8];
    float* out = (float*)d_out;

    __half *p_id, *p_md, *p_attp, *p_oo, *p_w1t, *p_wmt, *p_w2t, *p_memt, *p_xh, *p_memh;
    float *p_att;
    cudaGetSymbolAddress((void**)&p_id,   g_input_dot);
    cudaGetSymbolAddress((void**)&p_md,   g_memory_dot);
    cudaGetSymbolAddress((void**)&p_att,  g_att);
    cudaGetSymbolAddress((void**)&p_attp, g_attp);
    cudaGetSymbolAddress((void**)&p_oo,   g_out_one);
    cudaGetSymbolAddress((void**)&p_w1t,  g_w1t);
    cudaGetSymbolAddress((void**)&p_wmt,  g_wmt);
    cudaGetSymbolAddress((void**)&p_w2t,  g_w2t);
    cudaGetSymbolAddress((void**)&p_memt, g_memt);
    cudaGetSymbolAddress((void**)&p_xh,   g_xh);
    cudaGetSymbolAddress((void**)&p_memh, g_memh);

    cudaFuncSetAttribute(mma_gemm<ACT_RELU, false, false>,
                         cudaFuncAttributeMaxDynamicSharedMemorySize, GEMM_SMEM);
    cudaFuncSetAttribute(mma_gemm<ACT_NONE, false, true>,
                         cudaFuncAttributeMaxDynamicSharedMemorySize, GEMM_SMEM);
    cudaFuncSetAttribute(mma_gemm<ACT_NONE, false, false>,
                         cudaFuncAttributeMaxDynamicSharedMemorySize, GEMM_SMEM);
    cudaFuncSetAttribute(mma_gemm<ACT_GATE, true, true>,
                         cudaFuncAttributeMaxDynamicSharedMemorySize, GEMM_SMEM);

    // 0) fused operand conditioning, ONE launch
    prep_k<<<PREP_BLOCKS, 256>>>(x, mem, W1, Wm, W2,
                                 p_xh, p_memh, p_w1t, p_wmt, p_w2t, p_memt);

    // 1) input_dot = relu(x @ W1 + b1)            [16384,1024] K=1024, half out
    mma_gemm<ACT_RELU, false, false><<<dim3(HID / 256, (NB * LDQ) / 128, 1), 256, GEMM_SMEM>>>(
        p_xh, p_xh, p_w1t, b1, p_id, DIN, DIN, DIN, DIN, HID, 0, 0, 0, 1.0f);

    // 2) memory_dot = relu(mem @ Wm + bm)         [4096,1024]  K=1024, half out
    mma_gemm<ACT_RELU, false, false><<<dim3(HID / 256, (NB * LMEM) / 128, 1), 256, GEMM_SMEM>>>(
        p_memh, p_memh, p_wmt, bm, p_md, DIN, DIN, DIN, DIN, HID, 0, 0, 0, 1.0f);

    // 3) att = input_dot @ memory_dot^T / 32      [8][2048,512] K=1024, F32 out
    mma_gemm<ACT_NONE, false, true><<<dim3(LMEM / 256, LDQ / 128, NB), 256, GEMM_SMEM>>>(
        p_id, p_id, p_md, nullptr, p_att, HID, HID, HID, HID, LMEM,
        (long long)LDQ * HID, (long long)LMEM * HID, (long long)LDQ * LMEM, 1.0f / 32.0f);

    // 4) masked softmax: f32 logits -> fp16 probabilities
    softmax_w<<<(NB * LDQ) / 8, 256>>>(p_att, p_attp, mask);

    // 5) out_one = att @ mem                       [8][2048,1024] K=512, half out
    mma_gemm<ACT_NONE, false, false><<<dim3(DIN / 256, LDQ / 128, NB), 256, GEMM_SMEM>>>(
        p_attp, p_attp, p_memt, nullptr, p_oo, LMEM, LMEM, LMEM, LMEM, DIN,
        (long long)LDQ * LMEM, (long long)DIN * LMEM, (long long)LDQ * DIN, 1.0f);

    // 6) out = gate(concat(x, out_one) @ W2 + b2)  [16384,1024] K=2048, F32 out
    mma_gemm<ACT_GATE, true, true><<<dim3(HID / 256, (NB * LDQ) / 128, 1), 256, GEMM_SMEM>>>(
        p_xh, p_oo, p_w2t, b2, out, 2 * DIN, DIN, DIN, 2 * DIN, HID, 0, 0, 0, 1.0f);

    // 7) second tuple element: mem passthrough (exact)
    const int n4 = (NB * LMEM * DIN) / 4;
    copy_k<<<(n4 + 255) / 256, 256>>>((const float4*)mem,
                                      (float4*)(out + (size_t)NB * LDQ * HID), n4);
}

// round 9
// speedup vs baseline: 6.8828x; 1.1599x over previous
#include <cuda_runtime.h>
#include <cuda_fp16.h>
#include <cstdint>
#include <math.h>

#define NB   8
#define LDQ  2048
#define LMEM 512
#define DIN  1024
#define HID  1024

// ---------------- scratch (__device__ globals; no allocations allowed) ----
__device__ __half g_input_dot[(size_t)NB * LDQ * HID];   // 32 MB
__device__ __half g_memory_dot[(size_t)NB * LMEM * HID]; // 8 MB
__device__ float  g_att[(size_t)NB * LDQ * LMEM];        // 32 MB (f32 logits)
__device__ __half g_attp[(size_t)NB * LDQ * LMEM];       // 16 MB (fp16 probs)
__device__ __half g_out_one[(size_t)NB * LDQ * DIN];     // 32 MB
__device__ __half g_w1t[(size_t)DIN * HID];              // 2 MB
__device__ __half g_wmt[(size_t)DIN * HID];              // 2 MB
__device__ __half g_w2t[(size_t)2 * DIN * HID];          // 4 MB
__device__ __half g_memt[(size_t)NB * DIN * LMEM];       // 8 MB
__device__ __half g_xh[(size_t)NB * LDQ * DIN];          // 32 MB (x as fp16)
__device__ __half g_memh[(size_t)NB * LMEM * DIN];       // 8 MB (mem as fp16)

enum { ACT_NONE = 0, ACT_RELU = 1, ACT_GATE = 2 };

// ---------------- helpers --------------------------------------------------
__device__ __forceinline__ uint32_t smem_u32(const void* p) {
    uint32_t a;
    asm("{ .reg .u64 t; cvta.to.shared.u64 t, %1; cvt.u32.u64 %0, t; }" : "=r"(a) : "l"(p));
    return a;
}
// bit-cast __half2 -> u32 (this toolchain lacks __half2_as_uint)
__device__ __forceinline__ uint32_t h2u(__half2 h) {
    __half2_raw r = *reinterpret_cast<__half2_raw*>(&h);
    return (uint32_t)r.x | ((uint32_t)r.y << 16);
}

#define CP16(dst, src) \
    asm volatile("cp.async.cg.shared.global [%0], [%1], 16;" :: "r"(dst), "l"(src))
#define CP_COMMIT() asm volatile("cp.async.commit_group;")
#define CP_WAIT2()  asm volatile("cp.async.wait_group 2;")

// fp16 tensor-core mma, fp32 accumulate
__device__ __forceinline__ void mma_f16(float* d, const uint32_t* a, const uint32_t* b) {
    asm volatile(
        "mma.sync.aligned.m16n8k16.row.col.f32.f16.f16.f32 "
        "{%0,%1,%2,%3}, {%4,%5,%6,%7}, {%8,%9}, {%0,%1,%2,%3};"
        : "+f"(d[0]), "+f"(d[1]), "+f"(d[2]), "+f"(d[3])
        : "r"(a[0]), "r"(a[1]), "r"(a[2]), "r"(a[3]), "r"(b[0]), "r"(b[1]));
}

// ---------------- fp16 mma.sync NT GEMM: C[M,N] = A[M,K] * B[N,K]^T -------
// BM=128, BN=128, BK=32 halves. 128 threads, 4 warps (2x2), warp tile 64x64.
// 2 CTAs/SM (regs 208*128=26.6K/CTA, smem 80KB/CTA) -> co-resident CTA hides
// barrier/LDS-latency/epilogue bubbles of the other.
// 4-stage cp.async pipeline, one barrier per mainloop iteration.
// Smem rows: 32 halves data + 8 pad = 20 words (conflict-free permutation).
static constexpr int AROW_W = 20;                  // words per A/B smem row
static constexpr int ASZ = 128 * AROW_W;           // words per A stage
static constexpr int BSZ = 128 * AROW_W;           // words per B stage
static constexpr int STAGES = 4;
static constexpr int GEMM_SMEM = (ASZ + BSZ) * STAGES * 4;   // 81920 B

// Separate K indices: ka for the (possibly switched) A source, kb for B.
__device__ __forceinline__ void load_tile(
    uint32_t sb, int s, const __half* __restrict__ Ap, const __half* __restrict__ Bp,
    int m0, int n0, int ka, int kb, int lda, int ldb, int t)
{
    const uint32_t as = sb + s * (ASZ * 4);
    const uint32_t bs = sb + STAGES * (ASZ * 4) + s * (BSZ * 4);
    const int r  = t >> 2;            // 0..31
    const int c4 = (t & 3) * 4;       // word offset in row (16B chunks)
    const __half* ag = &Ap[(size_t)(m0 + r) * lda + ka + (t & 3) * 8];
#pragma unroll
    for (int q = 0; q < 4; q++)
        CP16(as + ((r + q * 32) * AROW_W + c4) * 4, ag + (size_t)(q * 32) * lda);
    const __half* bg = &Bp[(size_t)(n0 + r) * ldb + kb + (t & 3) * 8];
#pragma unroll
    for (int q = 0; q < 4; q++)
        CP16(bs + ((r + q * 32) * AROW_W + c4) * 4, bg + (size_t)(q * 32) * ldb);
    CP_COMMIT();
}

template <int ACT, bool DUALA, bool OUTF32>
__global__ void __launch_bounds__(128, 2)
mma_gemm(const __half* __restrict__ A1, const __half* __restrict__ A2,
         const __half* __restrict__ B, const float* __restrict__ bias,
         void* __restrict__ Cv,
         int K, int Ksplit, int lda, int ldb, int ldc,
         long long sA, long long sB, long long sC, float scale)
{
    extern __shared__ float sm[];
    const uint32_t sb = smem_u32(sm);

    const int t    = threadIdx.x;
    const int wid  = t >> 5;
    const int lane = t & 31;
    const int gid  = lane >> 2;      // 0..7
    const int tig  = lane & 3;       // 0..3
    const int z = blockIdx.z;
    A1 += (size_t)z * sA;
    A2 += (size_t)z * sA;
    B  += (size_t)z * sB;
    const int m0 = blockIdx.y * 128;
    const int n0 = blockIdx.x * 128;

    const int NI = K >> 5;           // BK = 32 halves

    // prologue: prefetch STAGES-1 = 3 stages
#pragma unroll
    for (int s = 0; s < 3; s++) {
        const int k0 = s * 32;
        const __half* Ap = A1;
        int ka = k0;
        if (DUALA && k0 >= Ksplit) { Ap = A2; ka = k0 - Ksplit; }
        load_tile(sb, s, Ap, B, m0, n0, ka, k0, lda, ldb, t);
    }

    float acc[4][8][4];
#pragma unroll
    for (int i = 0; i < 4; i++)
#pragma unroll
        for (int j = 0; j < 8; j++)
#pragma unroll
            for (int q = 0; q < 4; q++) acc[i][j][q] = 0.0f;

    const int mb = (wid >> 1) * 64;   // warp row offset in tile (2x2 warp grid)
    const int nb = (wid & 1) * 64;    // warp col offset in tile

    for (int i = 0; i < NI; i++) {
        CP_WAIT2();
        __syncthreads();   // compute of iter i-1 done on all warps ->
                           // writing stage (i+3)&3 == (i-1)&3 is WAR-safe.

        const int s = i & 3;
        const uint32_t* As_ = (const uint32_t*)(sm + s * ASZ);
        const uint32_t* Bs_ = (const uint32_t*)(sm + STAGES * ASZ + s * BSZ);

#pragma unroll
        for (int ks = 0; ks < 2; ks++) {          // two k16 steps
            const int kc = ks * 8 + tig;          // word index within row
            uint32_t af[4][4];
#pragma unroll
            for (int mi = 0; mi < 4; mi++) {
                const int r = mb + mi * 16 + gid;
                af[mi][0] = As_[r * AROW_W + kc];
                af[mi][1] = As_[(r + 8) * AROW_W + kc];
                af[mi][2] = As_[r * AROW_W + kc + 4];
                af[mi][3] = As_[(r + 8) * AROW_W + kc + 4];
            }
            uint32_t bf[8][2];
#pragma unroll
            for (int nj = 0; nj < 8; nj++) {
                const int n = nb + nj * 8 + gid;
                bf[nj][0] = Bs_[n * AROW_W + kc];
                bf[nj][1] = Bs_[n * AROW_W + kc + 4];
            }
#pragma unroll
            for (int mi = 0; mi < 4; mi++)
#pragma unroll
                for (int nj = 0; nj < 8; nj++)
                    mma_f16(acc[mi][nj], af[mi], bf[nj]);
        }

        const int nx = i + 3;
        if (nx < NI) {
            const int k0 = nx * 32;
            const __half* Ap = A1;
            int ka = k0;
            if (DUALA && k0 >= Ksplit) { Ap = A2; ka = k0 - Ksplit; }
            load_tile(sb, nx & 3, Ap, B, m0, n0, ka, k0, lda, ldb, t);
        } else {
            CP_COMMIT();   // keep group count in lockstep for CP_WAIT2
        }
    }

    // ---- epilogue ----
    float*  Cf = (float*)Cv  + (size_t)z * sC;
    __half* Ch = (__half*)Cv + (size_t)z * sC;
#pragma unroll
    for (int mi = 0; mi < 4; mi++) {
        const int r0 = m0 + mb + mi * 16 + gid;
#pragma unroll
        for (int nj = 0; nj < 8; nj++) {
            const int c0 = n0 + nb + nj * 8 + tig * 2;
            float v[4];
#pragma unroll
            for (int q = 0; q < 4; q++) v[q] = acc[mi][nj][q] * scale;
            if (ACT != ACT_NONE) {
                const float bb0 = __ldg(&bias[c0]);
                const float bb1 = __ldg(&bias[c0 + 1]);
                v[0] += bb0; v[1] += bb1; v[2] += bb0; v[3] += bb1;
            }
#pragma unroll
            for (int q = 0; q < 4; q++) {
                if (ACT == ACT_RELU) v[q] = fmaxf(v[q], 0.0f);
                if (ACT == ACT_GATE) {
                    const float sg = 1.0f / (1.0f + expf(-v[q]));
                    v[q] = sg * tanhf(v[q]);
                }
            }
            if (OUTF32) {
                *(float2*)&Cf[(size_t)r0 * ldc + c0]       = make_float2(v[0], v[1]);
                *(float2*)&Cf[(size_t)(r0 + 8) * ldc + c0] = make_float2(v[2], v[3]);
            } else {
                *(__half2*)&Ch[(size_t)r0 * ldc + c0] =
                    __floats2half2_rn(v[0], v[1]);
                *(__half2*)&Ch[(size_t)(r0 + 8) * ldc + c0] =
                    __floats2half2_rn(v[2], v[3]);
            }
        }
    }
}

// ---------------- fused prep: transposes + fp16 converts, ONE launch ------
__device__ __forceinline__ void do_transpose_h(
    const float* __restrict__ src, __half* __restrict__ dst,
    int R, int C, int tX, int tY, int t)
{
    __shared__ float tile[32][33];
    const int lx = t & 31, ly = t >> 5;   // 32 x 8
    const int x = tX * 32 + lx;
    const int y0 = tY * 32;
#pragma unroll
    for (int i = ly; i < 32; i += 8)
        tile[i][lx] = src[(size_t)(y0 + i) * C + x];
    __syncthreads();
    const int xo = tY * 32 + lx;
    const int yo0 = tX * 32;
#pragma unroll
    for (int i = ly; i < 32; i += 8)
        dst[(size_t)(yo0 + i) * R + xo] = __float2half_rn(tile[lx][i]);
}

static constexpr int PB_RX   = 16384;   // x -> half     (16M floats)
static constexpr int PB_RM   = 4096;    // mem -> half   (4M floats)
static constexpr int PB_W1   = 1024;    // W1t
static constexpr int PB_WM   = 1024;    // Wmt
static constexpr int PB_W2   = 2048;    // W2t
static constexpr int PB_MT   = 4096;    // memt (z=8)
static constexpr int PREP_BLOCKS = PB_RX + PB_RM + PB_W1 + PB_WM + PB_W2 + PB_MT;

__global__ void __launch_bounds__(256)
prep_k(const float* __restrict__ x, const float* __restrict__ mem,
       const float* __restrict__ W1, const float* __restrict__ Wm,
       const float* __restrict__ W2,
       __half* __restrict__ xh, __half* __restrict__ memh,
       __half* __restrict__ w1t, __half* __restrict__ wmt,
       __half* __restrict__ w2t, __half* __restrict__ memt)
{
    int b = blockIdx.x;
    const int t = threadIdx.x;
    if (b < PB_RX) {
        const int i = b * 256 + t;
        float4 v = ((const float4*)x)[i];
        ((uint2*)xh)[i] = make_uint2(
            h2u(__floats2half2_rn(v.x, v.y)),
            h2u(__floats2half2_rn(v.z, v.w)));
        return;
    }
    b -= PB_RX;
    if (b < PB_RM) {
        const int i = b * 256 + t;
        float4 v = ((const float4*)mem)[i];
        ((uint2*)memh)[i] = make_uint2(
            h2u(__floats2half2_rn(v.x, v.y)),
            h2u(__floats2half2_rn(v.z, v.w)));
        return;
    }
    b -= PB_RM;
    if (b < PB_W1) { do_transpose_h(W1, w1t, DIN, HID, b & 31, b >> 5, t); return; }
    b -= PB_W1;
    if (b < PB_WM) { do_transpose_h(Wm, wmt, DIN, HID, b & 31, b >> 5, t); return; }
    b -= PB_WM;
    if (b < PB_W2) { do_transpose_h(W2, w2t, 2 * DIN, HID, b & 31, b >> 5, t); return; }
    b -= PB_W2;
    {
        const int z = b >> 9;            // 512 tiles per batch (32 x 16)
        const int r = b & 511;
        do_transpose_h(mem + (size_t)z * LMEM * DIN, memt + (size_t)z * LMEM * DIN,
                       LMEM, DIN, r & 31, r >> 5, t);
    }
}

// ---------------- masked softmax: f32 logits in, fp16 probs out -----------
__global__ void softmax_w(const float* __restrict__ att, __half* __restrict__ attp,
                          const float* __restrict__ mask)
{
    const int gw = blockIdx.x * 8 + (threadIdx.x >> 5);
    const int lane = threadIdx.x & 31;
    const float4* p4 = (const float4*)(att + (size_t)gw * LMEM);
    const float4* m4 = (const float4*)(mask + (size_t)(gw >> 11) * LMEM);

    float4 v[4];
    float mx = -3.4e38f;
#pragma unroll
    for (int q = 0; q < 4; q++) {
        float4 a = p4[lane + q * 32];
        float4 mm = m4[lane + q * 32];
        a.x -= 1e30f * (1.0f - mm.x);
        a.y -= 1e30f * (1.0f - mm.y);
        a.z -= 1e30f * (1.0f - mm.z);
        a.w -= 1e30f * (1.0f - mm.w);
        v[q] = a;
        mx = fmaxf(mx, fmaxf(fmaxf(a.x, a.y), fmaxf(a.z, a.w)));
    }
#pragma unroll
    for (int s = 16; s > 0; s >>= 1)
        mx = fmaxf(mx, __shfl_xor_sync(0xffffffffu, mx, s));
    float sum = 0.0f;
#pragma unroll
    for (int q = 0; q < 4; q++) {
        v[q].x = __expf(v[q].x - mx);
        v[q].y = __expf(v[q].y - mx);
        v[q].z = __expf(v[q].z - mx);
        v[q].w = __expf(v[q].w - mx);
        sum += v[q].x + v[q].y + v[q].z + v[q].w;
    }
#pragma unroll
    for (int s = 16; s > 0; s >>= 1)
        sum += __shfl_xor_sync(0xffffffffu, sum, s);
    const float inv = 1.0f / sum;
    uint2* o2 = (uint2*)(attp + (size_t)gw * LMEM);   // 8B = 4 halves
#pragma unroll
    for (int q = 0; q < 4; q++) {
        o2[lane + q * 32] = make_uint2(
            h2u(__floats2half2_rn(v[q].x * inv, v[q].y * inv)),
            h2u(__floats2half2_rn(v[q].z * inv, v[q].w * inv)));
    }
}

__global__ void copy_k(const float4* __restrict__ src, float4* __restrict__ dst, int n4)
{
    int i = blockIdx.x * blockDim.x + threadIdx.x;
    if (i < n4) dst[i] = src[i];
}

// ---------------- launch ---------------------------------------------------
extern "C" void kernel_launch(void* const* d_in, const int* in_sizes, int n_in,
                              void* d_out, int out_size)
{
    const float* x    = (const float*)d_in[0];
    const float* mem  = (const float*)d_in[1];
    const float* mask = (const float*)d_in[2];
    const float* W1   = (const float*)d_in[3];
    const float* b1   = (const float*)d_in[4];
    const float* Wm   = (const float*)d_in[5];
    const float* bm   = (const float*)d_in[6];
    const float* W2   = (const float*)d_in[7];
    const float* b2   = (const float*)d_in[8];
    float* out = (float*)d_out;

    __half *p_id, *p_md, *p_attp, *p_oo, *p_w1t, *p_wmt, *p_w2t, *p_memt, *p_xh, *p_memh;
    float *p_att;
    cudaGetSymbolAddress((void**)&p_id,   g_input_dot);
    cudaGetSymbolAddress((void**)&p_md,   g_memory_dot);
    cudaGetSymbolAddress((void**)&p_att,  g_att);
    cudaGetSymbolAddress((void**)&p_attp, g_attp);
    cudaGetSymbolAddress((void**)&p_oo,   g_out_one);
    cudaGetSymbolAddress((void**)&p_w1t,  g_w1t);
    cudaGetSymbolAddress((void**)&p_wmt,  g_wmt);
    cudaGetSymbolAddress((void**)&p_w2t,  g_w2t);
    cudaGetSymbolAddress((void**)&p_memt, g_memt);
    cudaGetSymbolAddress((void**)&p_xh,   g_xh);
    cudaGetSymbolAddress((void**)&p_memh, g_memh);

    cudaFuncSetAttribute(mma_gemm<ACT_RELU, false, false>,
                         cudaFuncAttributeMaxDynamicSharedMemorySize, GEMM_SMEM);
    cudaFuncSetAttribute(mma_gemm<ACT_NONE, false, true>,
                         cudaFuncAttributeMaxDynamicSharedMemorySize, GEMM_SMEM);
    cudaFuncSetAttribute(mma_gemm<ACT_NONE, false, false>,
                         cudaFuncAttributeMaxDynamicSharedMemorySize, GEMM_SMEM);
    cudaFuncSetAttribute(mma_gemm<ACT_GATE, true, true>,
                         cudaFuncAttributeMaxDynamicSharedMemorySize, GEMM_SMEM);

    // 0) fused operand conditioning, ONE launch
    prep_k<<<PREP_BLOCKS, 256>>>(x, mem, W1, Wm, W2,
                                 p_xh, p_memh, p_w1t, p_wmt, p_w2t, p_memt);

    // 1) input_dot = relu(x @ W1 + b1)            [16384,1024] K=1024, half out
    mma_gemm<ACT_RELU, false, false><<<dim3(HID / 128, (NB * LDQ) / 128, 1), 128, GEMM_SMEM>>>(
        p_xh, p_xh, p_w1t, b1, p_id, DIN, DIN, DIN, DIN, HID, 0, 0, 0, 1.0f);

    // 2) memory_dot = relu(mem @ Wm + bm)         [4096,1024]  K=1024, half out
    mma_gemm<ACT_RELU, false, false><<<dim3(HID / 128, (NB * LMEM) / 128, 1), 128, GEMM_SMEM>>>(
        p_memh, p_memh, p_wmt, bm, p_md, DIN, DIN, DIN, DIN, HID, 0, 0, 0, 1.0f);

    // 3) att = input_dot @ memory_dot^T / 32      [8][2048,512] K=1024, F32 out
    mma_gemm<ACT_NONE, false, true><<<dim3(LMEM / 128, LDQ / 128, NB), 128, GEMM_SMEM>>>(
        p_id, p_id, p_md, nullptr, p_att, HID, HID, HID, HID, LMEM,
        (long long)LDQ * HID, (long long)LMEM * HID, (long long)LDQ * LMEM, 1.0f / 32.0f);

    // 4) masked softmax: f32 logits -> fp16 probabilities
    softmax_w<<<(NB * LDQ) / 8, 256>>>(p_att, p_attp, mask);

    // 5) out_one = att @ mem                       [8][2048,1024] K=512, half out
    mma_gemm<ACT_NONE, false, false><<<dim3(DIN / 128, LDQ / 128, NB), 128, GEMM_SMEM>>>(
        p_attp, p_attp, p_memt, nullptr, p_oo, LMEM, LMEM, LMEM, LMEM, DIN,
        (long long)LDQ * LMEM, (long long)DIN * LMEM, (long long)LDQ * DIN, 1.0f);

    // 6) out = gate(concat(x, out_one) @ W2 + b2)  [16384,1024] K=2048, F32 out
    mma_gemm<ACT_GATE, true, true><<<dim3(HID / 128, (NB * LDQ) / 128, 1), 128, GEMM_SMEM>>>(
        p_xh, p_oo, p_w2t, b2, out, 2 * DIN, DIN, DIN, 2 * DIN, HID, 0, 0, 0, 1.0f);

    // 7) second tuple element: mem passthrough (exact)
    const int n4 = (NB * LMEM * DIN) / 4;
    copy_k<<<(n4 + 255) / 256, 256>>>((const float4*)mem,
                                      (float4*)(out + (size_t)NB * LDQ * HID), n4);
}

// round 10
// speedup vs baseline: 7.5246x; 1.0933x over previous
#include <cuda_runtime.h>
#include <cuda_fp16.h>
#include <cstdint>
#include <math.h>

#define NB   8
#define LDQ  2048
#define LMEM 512
#define DIN  1024
#define HID  1024

// ---------------- scratch (__device__ globals; no allocations allowed) ----
__device__ __half g_input_dot[(size_t)NB * LDQ * HID];   // 32 MB
__device__ __half g_memory_dot[(size_t)NB * LMEM * HID]; // 8 MB
__device__ float  g_att[(size_t)NB * LDQ * LMEM];        // 32 MB (f32 logits)
__device__ __half g_attp[(size_t)NB * LDQ * LMEM];       // 16 MB (fp16 probs)
__device__ __half g_out_one[(size_t)NB * LDQ * DIN];     // 32 MB
__device__ __half g_w1t[(size_t)DIN * HID];              // 2 MB
__device__ __half g_wmt[(size_t)DIN * HID];              // 2 MB
__device__ __half g_w2t[(size_t)2 * DIN * HID];          // 4 MB
__device__ __half g_memt[(size_t)NB * DIN * LMEM];       // 8 MB
__device__ __half g_xh[(size_t)NB * LDQ * DIN];          // 32 MB (x as fp16)
__device__ __half g_memh[(size_t)NB * LMEM * DIN];       // 8 MB (mem as fp16)

enum { ACT_NONE = 0, ACT_RELU = 1, ACT_GATE = 2 };

// ---------------- helpers --------------------------------------------------
__device__ __forceinline__ uint32_t smem_u32(const void* p) {
    uint32_t a;
    asm("{ .reg .u64 t; cvta.to.shared.u64 t, %1; cvt.u32.u64 %0, t; }" : "=r"(a) : "l"(p));
    return a;
}
// bit-cast __half2 -> u32 (this toolchain lacks __half2_as_uint)
__device__ __forceinline__ uint32_t h2u(__half2 h) {
    __half2_raw r = *reinterpret_cast<__half2_raw*>(&h);
    return (uint32_t)r.x | ((uint32_t)r.y << 16);
}

#define CP16(dst, src) \
    asm volatile("cp.async.cg.shared.global [%0], [%1], 16;" :: "r"(dst), "l"(src))
#define CP_COMMIT() asm volatile("cp.async.commit_group;")
#define CP_WAIT2()  asm volatile("cp.async.wait_group 2;")

#define LDSM4(r0, r1, r2, r3, addr) \
    asm volatile("ldmatrix.sync.aligned.m8n8.x4.shared.b16 {%0,%1,%2,%3}, [%4];" \
        : "=r"(r0), "=r"(r1), "=r"(r2), "=r"(r3) : "r"(addr))

// fp16 tensor-core mma, fp32 accumulate
__device__ __forceinline__ void mma_f16(float* d, const uint32_t* a, const uint32_t* b) {
    asm volatile(
        "mma.sync.aligned.m16n8k16.row.col.f32.f16.f16.f32 "
        "{%0,%1,%2,%3}, {%4,%5,%6,%7}, {%8,%9}, {%0,%1,%2,%3};"
        : "+f"(d[0]), "+f"(d[1]), "+f"(d[2]), "+f"(d[3])
        : "r"(a[0]), "r"(a[1]), "r"(a[2]), "r"(a[3]), "r"(b[0]), "r"(b[1]));
}

// ---------------- fp16 mma.sync NT GEMM: C[M,N] = A[M,K] * B[N,K]^T -------
// BM=128, BN=128, BK=32 halves. 128 threads, 4 warps (2x2), warp tile 64x64.
// 2 CTAs/SM. 4-stage cp.async pipeline, one barrier per mainloop iteration.
// Fragments loaded via ldmatrix.m8n8.x4 (16 instr/iter vs 48 LDS.32).
// Smem rows: 32 halves data + 8 pad = 40 halves = 80 B (20 words). Row base
// addresses are 16B-aligned (80 = 5*16) and 8-row groups at stride 20 words
// cover all 32 banks ({20r mod 32} = {0,20,8,28,16,4,24,12}) -> conflict-free
// for both cp.async stores and ldmatrix reads.
static constexpr int AROW_W = 20;                  // words per A/B smem row
static constexpr int ASZ = 128 * AROW_W;           // words per A stage
static constexpr int BSZ = 128 * AROW_W;           // words per B stage
static constexpr int STAGES = 4;
static constexpr int GEMM_SMEM = (ASZ + BSZ) * STAGES * 4;   // 81920 B

// Separate K indices: ka for the (possibly switched) A source, kb for B.
__device__ __forceinline__ void load_tile(
    uint32_t sb, int s, const __half* __restrict__ Ap, const __half* __restrict__ Bp,
    int m0, int n0, int ka, int kb, int lda, int ldb, int t)
{
    const uint32_t as = sb + s * (ASZ * 4);
    const uint32_t bs = sb + STAGES * (ASZ * 4) + s * (BSZ * 4);
    const int r  = t >> 2;            // 0..31
    const int c4 = (t & 3) * 4;       // word offset in row (16B chunks)
    const __half* ag = &Ap[(size_t)(m0 + r) * lda + ka + (t & 3) * 8];
#pragma unroll
    for (int q = 0; q < 4; q++)
        CP16(as + ((r + q * 32) * AROW_W + c4) * 4, ag + (size_t)(q * 32) * lda);
    const __half* bg = &Bp[(size_t)(n0 + r) * ldb + kb + (t & 3) * 8];
#pragma unroll
    for (int q = 0; q < 4; q++)
        CP16(bs + ((r + q * 32) * AROW_W + c4) * 4, bg + (size_t)(q * 32) * ldb);
    CP_COMMIT();
}

template <int ACT, bool DUALA, bool OUTF32>
__global__ void __launch_bounds__(128, 2)
mma_gemm(const __half* __restrict__ A1, const __half* __restrict__ A2,
         const __half* __restrict__ B, const float* __restrict__ bias,
         void* __restrict__ Cv,
         int K, int Ksplit, int lda, int ldb, int ldc,
         long long sA, long long sB, long long sC, float scale)
{
    extern __shared__ float sm[];
    const uint32_t sb = smem_u32(sm);

    const int t    = threadIdx.x;
    const int wid  = t >> 5;
    const int lane = t & 31;
    const int gid  = lane >> 2;      // 0..7
    const int tig  = lane & 3;       // 0..3
    const int z = blockIdx.z;
    A1 += (size_t)z * sA;
    A2 += (size_t)z * sA;
    B  += (size_t)z * sB;
    const int m0 = blockIdx.y * 128;
    const int n0 = blockIdx.x * 128;

    const int NI = K >> 5;           // BK = 32 halves

    const int mb = (wid >> 1) * 64;   // warp row offset in tile (2x2 warp grid)
    const int nb = (wid & 1) * 64;    // warp col offset in tile

    // ldmatrix per-lane base addresses (bytes), stage/mi/ks offsets added later.
    // A x4 for (mi): matrices = {rows0-7 k0-7, rows8-15 k0-7, rows0-7 k8-15,
    // rows8-15 k8-15} -> regs a0..a3. Lane l supplies row (l&15), k-half (l>>4).
    const uint32_t a_lm = sb
        + (((mb + (lane & 15)) * AROW_W + (lane >> 4) * 4) << 2);
    // B x4 for group g (covers nj=2g, 2g+1): lanes 0-7 -> rows nj*8+0..7 k0-7,
    // 8-15 -> same rows k8-15, 16-23 -> rows+8 k0-7, 24-31 -> rows+8 k8-15
    // -> regs {b0[2g], b1[2g], b0[2g+1], b1[2g+1]}.
    const uint32_t b_lm = sb + STAGES * (ASZ * 4)
        + (((nb + (lane & 7) + ((lane >> 4) << 3)) * AROW_W + ((lane >> 3) & 1) * 4) << 2);

    // prologue: prefetch STAGES-1 = 3 stages
#pragma unroll
    for (int s = 0; s < 3; s++) {
        const int k0 = s * 32;
        const __half* Ap = A1;
        int ka = k0;
        if (DUALA && k0 >= Ksplit) { Ap = A2; ka = k0 - Ksplit; }
        load_tile(sb, s, Ap, B, m0, n0, ka, k0, lda, ldb, t);
    }

    float acc[4][8][4];
#pragma unroll
    for (int i = 0; i < 4; i++)
#pragma unroll
        for (int j = 0; j < 8; j++)
#pragma unroll
            for (int q = 0; q < 4; q++) acc[i][j][q] = 0.0f;

    for (int i = 0; i < NI; i++) {
        CP_WAIT2();
        __syncthreads();   // compute of iter i-1 done on all warps ->
                           // writing stage (i+3)&3 == (i-1)&3 is WAR-safe.

        const int s = i & 3;
        const uint32_t a_s = a_lm + s * (ASZ * 4);
        const uint32_t b_s = b_lm + s * (BSZ * 4);

#pragma unroll
        for (int ks = 0; ks < 2; ks++) {          // two k16 steps (+32 B each)
            uint32_t af[4][4];
#pragma unroll
            for (int mi = 0; mi < 4; mi++)
                LDSM4(af[mi][0], af[mi][1], af[mi][2], af[mi][3],
                      a_s + mi * (16 * AROW_W * 4) + ks * 32);
            uint32_t bf[8][2];
#pragma unroll
            for (int g = 0; g < 4; g++)
                LDSM4(bf[2 * g][0], bf[2 * g][1], bf[2 * g + 1][0], bf[2 * g + 1][1],
                      b_s + g * (16 * AROW_W * 4) + ks * 32);
#pragma unroll
            for (int mi = 0; mi < 4; mi++)
#pragma unroll
                for (int nj = 0; nj < 8; nj++)
                    mma_f16(acc[mi][nj], af[mi], bf[nj]);
        }

        const int nx = i + 3;
        if (nx < NI) {
            const int k0 = nx * 32;
            const __half* Ap = A1;
            int ka = k0;
            if (DUALA && k0 >= Ksplit) { Ap = A2; ka = k0 - Ksplit; }
            load_tile(sb, nx & 3, Ap, B, m0, n0, ka, k0, lda, ldb, t);
        } else {
            CP_COMMIT();   // keep group count in lockstep for CP_WAIT2
        }
    }

    // ---- epilogue ----
    float*  Cf = (float*)Cv  + (size_t)z * sC;
    __half* Ch = (__half*)Cv + (size_t)z * sC;
#pragma unroll
    for (int mi = 0; mi < 4; mi++) {
        const int r0 = m0 + mb + mi * 16 + gid;
#pragma unroll
        for (int nj = 0; nj < 8; nj++) {
            const int c0 = n0 + nb + nj * 8 + tig * 2;
            float v[4];
#pragma unroll
            for (int q = 0; q < 4; q++) v[q] = acc[mi][nj][q] * scale;
            if (ACT != ACT_NONE) {
                const float bb0 = __ldg(&bias[c0]);
                const float bb1 = __ldg(&bias[c0 + 1]);
                v[0] += bb0; v[1] += bb1; v[2] += bb0; v[3] += bb1;
            }
#pragma unroll
            for (int q = 0; q < 4; q++) {
                if (ACT == ACT_RELU) v[q] = fmaxf(v[q], 0.0f);
                if (ACT == ACT_GATE) {
                    const float sg = 1.0f / (1.0f + expf(-v[q]));
                    v[q] = sg * tanhf(v[q]);
                }
            }
            if (OUTF32) {
                *(float2*)&Cf[(size_t)r0 * ldc + c0]       = make_float2(v[0], v[1]);
                *(float2*)&Cf[(size_t)(r0 + 8) * ldc + c0] = make_float2(v[2], v[3]);
            } else {
                *(__half2*)&Ch[(size_t)r0 * ldc + c0] =
                    __floats2half2_rn(v[0], v[1]);
                *(__half2*)&Ch[(size_t)(r0 + 8) * ldc + c0] =
                    __floats2half2_rn(v[2], v[3]);
            }
        }
    }
}

// ---------------- fused prep: transposes + fp16 converts, ONE launch ------
__device__ __forceinline__ void do_transpose_h(
    const float* __restrict__ src, __half* __restrict__ dst,
    int R, int C, int tX, int tY, int t)
{
    __shared__ float tile[32][33];
    const int lx = t & 31, ly = t >> 5;   // 32 x 8
    const int x = tX * 32 + lx;
    const int y0 = tY * 32;
#pragma unroll
    for (int i = ly; i < 32; i += 8)
        tile[i][lx] = src[(size_t)(y0 + i) * C + x];
    __syncthreads();
    const int xo = tY * 32 + lx;
    const int yo0 = tX * 32;
#pragma unroll
    for (int i = ly; i < 32; i += 8)
        dst[(size_t)(yo0 + i) * R + xo] = __float2half_rn(tile[lx][i]);
}

static constexpr int PB_RX   = 16384;   // x -> half     (16M floats)
static constexpr int PB_RM   = 4096;    // mem -> half   (4M floats)
static constexpr int PB_W1   = 1024;    // W1t
static constexpr int PB_WM   = 1024;    // Wmt
static constexpr int PB_W2   = 2048;    // W2t
static constexpr int PB_MT   = 4096;    // memt (z=8)
static constexpr int PREP_BLOCKS = PB_RX + PB_RM + PB_W1 + PB_WM + PB_W2 + PB_MT;

__global__ void __launch_bounds__(256)
prep_k(const float* __restrict__ x, const float* __restrict__ mem,
       const float* __restrict__ W1, const float* __restrict__ Wm,
       const float* __restrict__ W2,
       __half* __restrict__ xh, __half* __restrict__ memh,
       __half* __restrict__ w1t, __half* __restrict__ wmt,
       __half* __restrict__ w2t, __half* __restrict__ memt)
{
    int b = blockIdx.x;
    const int t = threadIdx.x;
    if (b < PB_RX) {
        const int i = b * 256 + t;
        float4 v = ((const float4*)x)[i];
        ((uint2*)xh)[i] = make_uint2(
            h2u(__floats2half2_rn(v.x, v.y)),
            h2u(__floats2half2_rn(v.z, v.w)));
        return;
    }
    b -= PB_RX;
    if (b < PB_RM) {
        const int i = b * 256 + t;
        float4 v = ((const float4*)mem)[i];
        ((uint2*)memh)[i] = make_uint2(
            h2u(__floats2half2_rn(v.x, v.y)),
            h2u(__floats2half2_rn(v.z, v.w)));
        return;
    }
    b -= PB_RM;
    if (b < PB_W1) { do_transpose_h(W1, w1t, DIN, HID, b & 31, b >> 5, t); return; }
    b -= PB_W1;
    if (b < PB_WM) { do_transpose_h(Wm, wmt, DIN, HID, b & 31, b >> 5, t); return; }
    b -= PB_WM;
    if (b < PB_W2) { do_transpose_h(W2, w2t, 2 * DIN, HID, b & 31, b >> 5, t); return; }
    b -= PB_W2;
    {
        const int z = b >> 9;            // 512 tiles per batch (32 x 16)
        const int r = b & 511;
        do_transpose_h(mem + (size_t)z * LMEM * DIN, memt + (size_t)z * LMEM * DIN,
                       LMEM, DIN, r & 31, r >> 5, t);
    }
}

// ---------------- masked softmax: f32 logits in, fp16 probs out -----------
__global__ void softmax_w(const float* __restrict__ att, __half* __restrict__ attp,
                          const float* __restrict__ mask)
{
    const int gw = blockIdx.x * 8 + (threadIdx.x >> 5);
    const int lane = threadIdx.x & 31;
    const float4* p4 = (const float4*)(att + (size_t)gw * LMEM);
    const float4* m4 = (const float4*)(mask + (size_t)(gw >> 11) * LMEM);

    float4 v[4];
    float mx = -3.4e38f;
#pragma unroll
    for (int q = 0; q < 4; q++) {
        float4 a = p4[lane + q * 32];
        float4 mm = m4[lane + q * 32];
        a.x -= 1e30f * (1.0f - mm.x);
        a.y -= 1e30f * (1.0f - mm.y);
        a.z -= 1e30f * (1.0f - mm.z);
        a.w -= 1e30f * (1.0f - mm.w);
        v[q] = a;
        mx = fmaxf(mx, fmaxf(fmaxf(a.x, a.y), fmaxf(a.z, a.w)));
    }
#pragma unroll
    for (int s = 16; s > 0; s >>= 1)
        mx = fmaxf(mx, __shfl_xor_sync(0xffffffffu, mx, s));
    float sum = 0.0f;
#pragma unroll
    for (int q = 0; q < 4; q++) {
        v[q].x = __expf(v[q].x - mx);
        v[q].y = __expf(v[q].y - mx);
        v[q].z = __expf(v[q].z - mx);
        v[q].w = __expf(v[q].w - mx);
        sum += v[q].x + v[q].y + v[q].z + v[q].w;
    }
#pragma unroll
    for (int s = 16; s > 0; s >>= 1)
        sum += __shfl_xor_sync(0xffffffffu, sum, s);
    const float inv = 1.0f / sum;
    uint2* o2 = (uint2*)(attp + (size_t)gw * LMEM);   // 8B = 4 halves
#pragma unroll
    for (int q = 0; q < 4; q++) {
        o2[lane + q * 32] = make_uint2(
            h2u(__floats2half2_rn(v[q].x * inv, v[q].y * inv)),
            h2u(__floats2half2_rn(v[q].z * inv, v[q].w * inv)));
    }
}

__global__ void copy_k(const float4* __restrict__ src, float4* __restrict__ dst, int n4)
{
    int i = blockIdx.x * blockDim.x + threadIdx.x;
    if (i < n4) dst[i] = src[i];
}

// ---------------- launch ---------------------------------------------------
extern "C" void kernel_launch(void* const* d_in, const int* in_sizes, int n_in,
                              void* d_out, int out_size)
{
    const float* x    = (const float*)d_in[0];
    const float* mem  = (const float*)d_in[1];
    const float* mask = (const float*)d_in[2];
    const float* W1   = (const float*)d_in[3];
    const float* b1   = (const float*)d_in[4];
    const float* Wm   = (const float*)d_in[5];
    const float* bm   = (const float*)d_in[6];
    const float* W2   = (const float*)d_in[7];
    const float* b2   = (const float*)d_in[8];
    float* out = (float*)d_out;

    __half *p_id, *p_md, *p_attp, *p_oo, *p_w1t, *p_wmt, *p_w2t, *p_memt, *p_xh, *p_memh;
    float *p_att;
    cudaGetSymbolAddress((void**)&p_id,   g_input_dot);
    cudaGetSymbolAddress((void**)&p_md,   g_memory_dot);
    cudaGetSymbolAddress((void**)&p_att,  g_att);
    cudaGetSymbolAddress((void**)&p_attp, g_attp);
    cudaGetSymbolAddress((void**)&p_oo,   g_out_one);
    cudaGetSymbolAddress((void**)&p_w1t,  g_w1t);
    cudaGetSymbolAddress((void**)&p_wmt,  g_wmt);
    cudaGetSymbolAddress((void**)&p_w2t,  g_w2t);
    cudaGetSymbolAddress((void**)&p_memt, g_memt);
    cudaGetSymbolAddress((void**)&p_xh,   g_xh);
    cudaGetSymbolAddress((void**)&p_memh, g_memh);

    cudaFuncSetAttribute(mma_gemm<ACT_RELU, false, false>,
                         cudaFuncAttributeMaxDynamicSharedMemorySize, GEMM_SMEM);
    cudaFuncSetAttribute(mma_gemm<ACT_NONE, false, true>,
                         cudaFuncAttributeMaxDynamicSharedMemorySize, GEMM_SMEM);
    cudaFuncSetAttribute(mma_gemm<ACT_NONE, false, false>,
                         cudaFuncAttributeMaxDynamicSharedMemorySize, GEMM_SMEM);
    cudaFuncSetAttribute(mma_gemm<ACT_GATE, true, true>,
                         cudaFuncAttributeMaxDynamicSharedMemorySize, GEMM_SMEM);

    // 0) fused operand conditioning, ONE launch
    prep_k<<<PREP_BLOCKS, 256>>>(x, mem, W1, Wm, W2,
                                 p_xh, p_memh, p_w1t, p_wmt, p_w2t, p_memt);

    // 1) input_dot = relu(x @ W1 + b1)            [16384,1024] K=1024, half out
    mma_gemm<ACT_RELU, false, false><<<dim3(HID / 128, (NB * LDQ) / 128, 1), 128, GEMM_SMEM>>>(
        p_xh, p_xh, p_w1t, b1, p_id, DIN, DIN, DIN, DIN, HID, 0, 0, 0, 1.0f);

    // 2) memory_dot = relu(mem @ Wm + bm)         [4096,1024]  K=1024, half out
    mma_gemm<ACT_RELU, false, false><<<dim3(HID / 128, (NB * LMEM) / 128, 1), 128, GEMM_SMEM>>>(
        p_memh, p_memh, p_wmt, bm, p_md, DIN, DIN, DIN, DIN, HID, 0, 0, 0, 1.0f);

    // 3) att = input_dot @ memory_dot^T / 32      [8][2048,512] K=1024, F32 out
    mma_gemm<ACT_NONE, false, true><<<dim3(LMEM / 128, LDQ / 128, NB), 128, GEMM_SMEM>>>(
        p_id, p_id, p_md, nullptr, p_att, HID, HID, HID, HID, LMEM,
        (long long)LDQ * HID, (long long)LMEM * HID, (long long)LDQ * LMEM, 1.0f / 32.0f);

    // 4) masked softmax: f32 logits -> fp16 probabilities
    softmax_w<<<(NB * LDQ) / 8, 256>>>(p_att, p_attp, mask);

    // 5) out_one = att @ mem                       [8][2048,1024] K=512, half out
    mma_gemm<ACT_NONE, false, false><<<dim3(DIN / 128, LDQ / 128, NB), 128, GEMM_SMEM>>>(
        p_attp, p_attp, p_memt, nullptr, p_oo, LMEM, LMEM, LMEM, LMEM, DIN,
        (long long)LDQ * LMEM, (long long)DIN * LMEM, (long long)LDQ * DIN, 1.0f);

    // 6) out = gate(concat(x, out_one) @ W2 + b2)  [16384,1024] K=2048, F32 out
    mma_gemm<ACT_GATE, true, true><<<dim3(HID / 128, (NB * LDQ) / 128, 1), 128, GEMM_SMEM>>>(
        p_xh, p_oo, p_w2t, b2, out, 2 * DIN, DIN, DIN, 2 * DIN, HID, 0, 0, 0, 1.0f);

    // 7) second tuple element: mem passthrough (exact)
    const int n4 = (NB * LMEM * DIN) / 4;
    copy_k<<<(n4 + 255) / 256, 256>>>((const float4*)mem,
                                      (float4*)(out + (size_t)NB * LDQ * HID), n4);
}